// round 5
// baseline (speedup 1.0000x reference)
#include <cuda_runtime.h>
#include <cuda_bf16.h>

// ---------------------------------------------------------------------------
// GAT layer, fused:
//   k1: H = X @ W                    (fp32 SGEMM, 128x128 tiles)
//   k2: as = H@a_self, an = H@a_neighs; H rounded in-place to tf32 (RNA)
//   k3: Out = elu( (P @ H) / rowsum(P) ),
//       P_ij = adj_ij>0 ? exp(leakyrelu((as_i+an_j)*M_ij)) : 0
//       P computed on the fly per 64x64 tile, P@H via mma.sync tf32.
// No max-subtraction needed: logits are small, exp() is safe in fp32.
// ---------------------------------------------------------------------------

#define NROWS 8192
#define IND   512
#define OUTD  256

// scratch (static device globals — no allocation)
__device__ __align__(16) float g_h[NROWS * OUTD];
__device__ __align__(16) float g_as[NROWS];
__device__ __align__(16) float g_an[NROWS];

// ---------------------------------------------------------------------------
// helpers
// ---------------------------------------------------------------------------
__device__ __forceinline__ float to_tf32(float x) {
    unsigned r;
    asm("cvt.rna.tf32.f32 %0, %1;\n" : "=r"(r) : "f"(x));
    return __uint_as_float(r);
}

__device__ __forceinline__ void mma_tf32(float* d, const unsigned* a,
                                         unsigned b0, unsigned b1) {
    asm volatile(
        "mma.sync.aligned.m16n8k8.row.col.f32.tf32.tf32.f32 "
        "{%0,%1,%2,%3}, {%4,%5,%6,%7}, {%8,%9}, {%0,%1,%2,%3};\n"
        : "+f"(d[0]), "+f"(d[1]), "+f"(d[2]), "+f"(d[3])
        : "r"(a[0]), "r"(a[1]), "r"(a[2]), "r"(a[3]), "r"(b0), "r"(b1));
}

__device__ __forceinline__ void cp16(void* smem, const void* g) {
    unsigned s = (unsigned)__cvta_generic_to_shared(smem);
    asm volatile("cp.async.cg.shared.global [%0], [%1], 16;\n" :: "r"(s), "l"(g));
}

__device__ __forceinline__ float elu_f(float x) {
    return x > 0.f ? x : expm1f(x);
}

// ---------------------------------------------------------------------------
// Kernel 1: H = X @ W   (8192x512 @ 512x256, fp32)
// 128x128 tile per CTA, BK=16, 256 threads, 8x8 per thread (split 4+4).
// grid = (2, 64)
// ---------------------------------------------------------------------------
__global__ __launch_bounds__(256) void k1_gemm_xw(const float* __restrict__ X,
                                                  const float* __restrict__ W) {
    __shared__ float As[16][132];
    __shared__ float Bs[16][132];
    const int tid = threadIdx.x;
    const int tx = tid & 15, ty = tid >> 4;
    const int m0 = blockIdx.y * 128, n0 = blockIdx.x * 128;

    float acc[8][8];
#pragma unroll
    for (int i = 0; i < 8; i++)
#pragma unroll
        for (int j = 0; j < 8; j++) acc[i][j] = 0.f;

    for (int k0 = 0; k0 < IND; k0 += 16) {
#pragma unroll
        for (int p = 0; p < 2; p++) {               // A tile 128x16 (transposed store)
            int r = (tid >> 2) + p * 64;
            int c = (tid & 3) * 4;
            float4 v = *(const float4*)&X[(size_t)(m0 + r) * IND + k0 + c];
            As[c + 0][r] = v.x; As[c + 1][r] = v.y;
            As[c + 2][r] = v.z; As[c + 3][r] = v.w;
        }
#pragma unroll
        for (int p = 0; p < 2; p++) {               // B tile 16x128
            int r = (tid >> 5) + p * 8;
            int c = (tid & 31) * 4;
            *(float4*)&Bs[r][c] = *(const float4*)&W[(size_t)(k0 + r) * OUTD + n0 + c];
        }
        __syncthreads();
#pragma unroll
        for (int k = 0; k < 16; k++) {
            float a[8], b[8];
            *(float4*)&a[0] = *(float4*)&As[k][ty * 4];
            *(float4*)&a[4] = *(float4*)&As[k][64 + ty * 4];
            *(float4*)&b[0] = *(float4*)&Bs[k][tx * 4];
            *(float4*)&b[4] = *(float4*)&Bs[k][64 + tx * 4];
#pragma unroll
            for (int i = 0; i < 8; i++)
#pragma unroll
                for (int j = 0; j < 8; j++) acc[i][j] += a[i] * b[j];
        }
        __syncthreads();
    }
#pragma unroll
    for (int i = 0; i < 8; i++) {
        int r = m0 + (i < 4 ? ty * 4 + i : 64 + ty * 4 + (i - 4));
        float4 v0 = make_float4(acc[i][0], acc[i][1], acc[i][2], acc[i][3]);
        float4 v1 = make_float4(acc[i][4], acc[i][5], acc[i][6], acc[i][7]);
        *(float4*)&g_h[(size_t)r * OUTD + n0 + tx * 4] = v0;
        *(float4*)&g_h[(size_t)r * OUTD + n0 + 64 + tx * 4] = v1;
    }
}

// ---------------------------------------------------------------------------
// Kernel 2: as/an row dots; round H to tf32 (RNA) in place.
// 1 warp per row; grid = 1024, block = 256.
// ---------------------------------------------------------------------------
__global__ __launch_bounds__(256) void k2_attvec(const float* __restrict__ a_self,
                                                 const float* __restrict__ a_neighs) {
    const int warp = threadIdx.x >> 5, lane = threadIdx.x & 31;
    const int row = blockIdx.x * 8 + warp;
    float4* h4 = (float4*)&g_h[(size_t)row * OUTD];
    float s1 = 0.f, s2 = 0.f;
#pragma unroll
    for (int q = 0; q < 2; q++) {
        float4 v = h4[lane + 32 * q];
        float4 a = ((const float4*)a_self)[lane + 32 * q];
        float4 b = ((const float4*)a_neighs)[lane + 32 * q];
        s1 += v.x * a.x + v.y * a.y + v.z * a.z + v.w * a.w;
        s2 += v.x * b.x + v.y * b.y + v.z * b.z + v.w * b.w;
        float4 t;
        t.x = to_tf32(v.x); t.y = to_tf32(v.y);
        t.z = to_tf32(v.z); t.w = to_tf32(v.w);
        h4[lane + 32 * q] = t;
    }
#pragma unroll
    for (int off = 16; off >= 1; off >>= 1) {
        s1 += __shfl_xor_sync(0xffffffffu, s1, off);
        s2 += __shfl_xor_sync(0xffffffffu, s2, off);
    }
    if (lane == 0) { g_as[row] = s1; g_an[row] = s2; }
}

// ---------------------------------------------------------------------------
// Kernel 3: fused masked-exp attention GEMM.
// CTA: 64 output rows x full 256 cols; loop over 128 k-tiles of 64 columns.
// cp.async double-buffered staging of M / adj / H tiles; P computed into
// shared (tf32); P@H via mma.sync m16n8k8 tf32 (8 warps x 64x32 each).
// grid = 128, block = 256, dyn smem = 218624 B.
// ---------------------------------------------------------------------------
#define SMEM_FLOATS 54656
#define SMEM_BYTES  (SMEM_FLOATS * 4)

__global__ __launch_bounds__(256) void k3_attn(const float* __restrict__ Adj,
                                               const float* __restrict__ Mg,
                                               float* __restrict__ Out) {
    extern __shared__ float sm[];
    float* sM   = sm;                 // 2 x 64x64
    float* sA   = sm + 8192;          // 2 x 64x64
    float* sH   = sm + 16384;         // 2 x 64x264 (padded)
    float* sP   = sm + 50176;         // 64x68 (padded)
    float* s_as = sm + 54528;         // 64
    float* s_rs = sm + 54592;         // 64

    const int tid = threadIdx.x;
    const int lane = tid & 31, warp = tid >> 5;
    const int rowbase = blockIdx.x * 64;

    if (tid < 16)
        *(float4*)&s_as[tid * 4] = *(const float4*)&g_as[rowbase + tid * 4];

    auto stage = [&](int tt) {
        const int b = tt & 1;
        const int jb = tt * 64;
#pragma unroll
        for (int p = 0; p < 4; p++) {             // M + adj tiles (64x64 each)
            int ch = tid + p * 256;
            int r = ch >> 4, c = (ch & 15) << 2;
            size_t goff = (size_t)(rowbase + r) * NROWS + jb + c;
            cp16(&sM[b * 4096 + r * 64 + c], Mg + goff);
            cp16(&sA[b * 4096 + r * 64 + c], Adj + goff);
        }
#pragma unroll
        for (int p = 0; p < 16; p++) {            // H tile (64x256)
            int ch = tid + p * 256;
            int r = ch >> 6, c = (ch & 63) << 2;
            cp16(&sH[b * 16896 + r * 264 + c], &g_h[(size_t)(jb + r) * OUTD + c]);
        }
        asm volatile("cp.async.commit_group;\n" ::: "memory");
    };

    float rsum[4] = {0.f, 0.f, 0.f, 0.f};
    float acc[4][4][4] = {};

    stage(0);
    for (int t = 0; t < 128; t++) {
        const int b = t & 1;
        if (t + 1 < 128) {
            stage(t + 1);
            asm volatile("cp.async.wait_group 1;\n" ::: "memory");
        } else {
            asm volatile("cp.async.wait_group 0;\n" ::: "memory");
        }
        __syncthreads();

        // ---- compute P tile (each thread: 4 rows x 4 cols) ----
        {
            const int g = tid >> 4;
            const int c = (tid & 15) << 2;
            float4 an4 = *(const float4*)&g_an[t * 64 + c];
#pragma unroll
            for (int it = 0; it < 4; it++) {
                const int r = g + (it << 4);
                const float asr = s_as[r];
                float4 m4 = *(float4*)&sM[b * 4096 + r * 64 + c];
                float4 a4 = *(float4*)&sA[b * 4096 + r * 64 + c];
                float t0 = (asr + an4.x) * m4.x; t0 = t0 > 0.f ? t0 : 0.2f * t0;
                float t1 = (asr + an4.y) * m4.y; t1 = t1 > 0.f ? t1 : 0.2f * t1;
                float t2 = (asr + an4.z) * m4.z; t2 = t2 > 0.f ? t2 : 0.2f * t2;
                float t3 = (asr + an4.w) * m4.w; t3 = t3 > 0.f ? t3 : 0.2f * t3;
                float p0 = a4.x > 0.f ? __expf(t0) : 0.f;
                float p1 = a4.y > 0.f ? __expf(t1) : 0.f;
                float p2 = a4.z > 0.f ? __expf(t2) : 0.f;
                float p3 = a4.w > 0.f ? __expf(t3) : 0.f;
                rsum[it] += (p0 + p1) + (p2 + p3);
                float4 pv = make_float4(to_tf32(p0), to_tf32(p1),
                                        to_tf32(p2), to_tf32(p3));
                *(float4*)&sP[r * 68 + c] = pv;
            }
        }
        __syncthreads();

        // ---- P @ H via tf32 mma: warp w -> cols [32w, 32w+32) ----
        {
            const int r0 = lane >> 2, c0 = lane & 3;
            const int nb = warp * 32;
#pragma unroll
            for (int k8 = 0; k8 < 8; k8++) {
                const int kb = k8 << 3;
                unsigned afr[4][4];
#pragma unroll
                for (int mt = 0; mt < 4; mt++) {
                    const float* ap = &sP[(mt * 16 + r0) * 68 + kb + c0];
                    afr[mt][0] = __float_as_uint(ap[0]);
                    afr[mt][1] = __float_as_uint(ap[8 * 68]);
                    afr[mt][2] = __float_as_uint(ap[4]);
                    afr[mt][3] = __float_as_uint(ap[8 * 68 + 4]);
                }
                const float* hp = &sH[b * 16896 + (kb + c0) * 264 + nb + r0];
#pragma unroll
                for (int nt = 0; nt < 4; nt++) {
                    unsigned b0 = __float_as_uint(hp[nt * 8]);
                    unsigned b1 = __float_as_uint(hp[4 * 264 + nt * 8]);
#pragma unroll
                    for (int mt = 0; mt < 4; mt++)
                        mma_tf32(acc[mt][nt], afr[mt], b0, b1);
                }
            }
        }
        __syncthreads();
    }

    // ---- rowsum reduction (16 threads share a row; no atomics) ----
#pragma unroll
    for (int off = 8; off >= 1; off >>= 1)
#pragma unroll
        for (int it = 0; it < 4; it++)
            rsum[it] += __shfl_xor_sync(0xffffffffu, rsum[it], off);
    if ((lane & 15) == 0) {
        const int g = tid >> 4;
#pragma unroll
        for (int it = 0; it < 4; it++) s_rs[g + (it << 4)] = rsum[it];
    }
    __syncthreads();

    // ---- epilogue: divide, elu, store ----
    {
        const int r0 = lane >> 2, c0 = lane & 3;
#pragma unroll
        for (int mt = 0; mt < 4; mt++) {
            const int ra = mt * 16 + r0;
            const float ia = 1.0f / s_rs[ra];
            const float ib = 1.0f / s_rs[ra + 8];
#pragma unroll
            for (int nt = 0; nt < 4; nt++) {
                const int col = warp * 32 + nt * 8 + c0 * 2;
                float2 va = make_float2(elu_f(acc[mt][nt][0] * ia),
                                        elu_f(acc[mt][nt][1] * ia));
                float2 vb = make_float2(elu_f(acc[mt][nt][2] * ib),
                                        elu_f(acc[mt][nt][3] * ib));
                *(float2*)&Out[(size_t)(rowbase + ra) * OUTD + col] = va;
                *(float2*)&Out[(size_t)(rowbase + ra + 8) * OUTD + col] = vb;
            }
        }
    }
}

// ---------------------------------------------------------------------------
extern "C" void kernel_launch(void* const* d_in, const int* in_sizes, int n_in,
                              void* d_out, int out_size) {
    const float* X        = (const float*)d_in[0];
    const float* Adj      = (const float*)d_in[1];
    const float* Mg       = (const float*)d_in[2];
    const float* W        = (const float*)d_in[3];
    const float* a_self   = (const float*)d_in[4];
    const float* a_neighs = (const float*)d_in[5];
    float* Out = (float*)d_out;

    cudaFuncSetAttribute(k3_attn, cudaFuncAttributeMaxDynamicSharedMemorySize,
                         SMEM_BYTES);

    k1_gemm_xw<<<dim3(2, 64), 256>>>(X, W);
    k2_attvec<<<1024, 256>>>(a_self, a_neighs);
    k3_attn<<<128, 256, SMEM_BYTES>>>(Adj, Mg, Out);
}

// round 6
// speedup vs baseline: 1.1045x; 1.1045x over previous
#include <cuda_runtime.h>
#include <cuda_bf16.h>

// ---------------------------------------------------------------------------
// GAT layer:
//   k1: H = X @ W                    (tf32 mma.sync, RNA-rounded staging)
//   k2: as = H@a_self, an = H@a_neighs; H rounded in-place to tf32 (RNA)
//   k3: Out = elu( (P @ H) / rowsum(P) ),
//       P_ij = adj_ij>0 ? exp(leakyrelu((as_i+an_j)*M_ij)) : 0
//   k3 pipeline: 1 barrier/tile, M/adj via register LDG prefetch (no smem),
//   P double-buffered, A-frags via ldmatrix, exp overlapped with HMMA.
// ---------------------------------------------------------------------------

#define NROWS 8192
#define IND   512
#define OUTD  256

__device__ __align__(16) float g_h[NROWS * OUTD];
__device__ __align__(16) float g_as[NROWS];
__device__ __align__(16) float g_an[NROWS];

// ---------------------------------------------------------------------------
__device__ __forceinline__ float to_tf32(float x) {
    unsigned r;
    asm("cvt.rna.tf32.f32 %0, %1;\n" : "=r"(r) : "f"(x));
    return __uint_as_float(r);
}

__device__ __forceinline__ void mma_tf32(float* d, const unsigned* a,
                                         unsigned b0, unsigned b1) {
    asm volatile(
        "mma.sync.aligned.m16n8k8.row.col.f32.tf32.tf32.f32 "
        "{%0,%1,%2,%3}, {%4,%5,%6,%7}, {%8,%9}, {%0,%1,%2,%3};\n"
        : "+f"(d[0]), "+f"(d[1]), "+f"(d[2]), "+f"(d[3])
        : "r"(a[0]), "r"(a[1]), "r"(a[2]), "r"(a[3]), "r"(b0), "r"(b1));
}

__device__ __forceinline__ void ldsm4(unsigned* a, unsigned addr) {
    asm volatile(
        "ldmatrix.sync.aligned.m8n8.x4.shared.b16 {%0,%1,%2,%3}, [%4];\n"
        : "=r"(a[0]), "=r"(a[1]), "=r"(a[2]), "=r"(a[3]) : "r"(addr));
}

__device__ __forceinline__ void cp16(void* smem, const void* g) {
    unsigned s = (unsigned)__cvta_generic_to_shared(smem);
    asm volatile("cp.async.cg.shared.global [%0], [%1], 16;\n" :: "r"(s), "l"(g));
}

__device__ __forceinline__ float elu_f(float x) {
    return x > 0.f ? x : expm1f(x);
}

// ---------------------------------------------------------------------------
// Kernel 1: H = X @ W, tf32 tensor cores. Tile 128x128, BK=32, 256 thr.
// grid (2, 64). smem: sX[2][128*36] + sW[2][32*136] = 71680 B dynamic.
// ---------------------------------------------------------------------------
#define K1_SMEM_BYTES ((2 * 128 * 36 + 2 * 32 * 136) * 4)

__global__ __launch_bounds__(256) void k1_gemm_xw(const float* __restrict__ X,
                                                  const float* __restrict__ W) {
    extern __shared__ float sm1[];
    float* sX = sm1;                   // 2 x 128 x 36
    float* sW = sm1 + 2 * 128 * 36;    // 2 x 32 x 136

    const int tid = threadIdx.x;
    const int lane = tid & 31, warp = tid >> 5;
    const int wr = warp & 3, wc = warp >> 2;     // warp tile 32(m) x 64(n)
    const int m0 = blockIdx.y * 128, n0 = blockIdx.x * 128;
    const int r0 = lane >> 2, c0 = lane & 3;

    // ldmatrix lane addressing (A-frag from sX)
    const int sel = lane >> 3, mrow = lane & 7;
    const int lrow = ((sel & 1) << 3) + mrow, lcol = (sel >> 1) << 2;
    const unsigned sX_u = (unsigned)__cvta_generic_to_shared(sX);

    float acc[2][8][4] = {};
    float4 xv[4], wv[4];

    auto ldg_stage = [&](int k0) {
#pragma unroll
        for (int p = 0; p < 4; p++) {
            int q = tid + p * 256;
            xv[p] = *(const float4*)&X[(size_t)(m0 + (q >> 3)) * IND + k0 + ((q & 7) << 2)];
            wv[p] = *(const float4*)&W[(size_t)(k0 + (q >> 5)) * OUTD + n0 + ((q & 31) << 2)];
        }
    };
    auto sts_stage = [&](int buf) {
#pragma unroll
        for (int p = 0; p < 4; p++) {
            int q = tid + p * 256;
            float4 t = make_float4(to_tf32(xv[p].x), to_tf32(xv[p].y),
                                   to_tf32(xv[p].z), to_tf32(xv[p].w));
            *(float4*)&sX[buf * 4608 + (q >> 3) * 36 + ((q & 7) << 2)] = t;
            float4 u = make_float4(to_tf32(wv[p].x), to_tf32(wv[p].y),
                                   to_tf32(wv[p].z), to_tf32(wv[p].w));
            *(float4*)&sW[buf * 4352 + (q >> 5) * 136 + ((q & 31) << 2)] = u;
        }
    };

    ldg_stage(0);
    sts_stage(0);
    __syncthreads();

    for (int s = 0; s < 16; s++) {
        const int buf = s & 1;
        if (s < 15) ldg_stage((s + 1) * 32);
#pragma unroll
        for (int k8 = 0; k8 < 4; k8++) {
            const int kb = k8 << 3;
            unsigned afr[2][4];
#pragma unroll
            for (int mt = 0; mt < 2; mt++) {
                unsigned addr = sX_u +
                    (buf * 4608 + (wr * 32 + mt * 16 + lrow) * 36 + kb + lcol) * 4u;
                ldsm4(afr[mt], addr);
            }
            const float* wp = &sW[buf * 4352 + (kb + c0) * 136 + wc * 64 + r0];
#pragma unroll
            for (int nt = 0; nt < 8; nt++) {
                unsigned b0 = __float_as_uint(wp[nt * 8]);
                unsigned b1 = __float_as_uint(wp[4 * 136 + nt * 8]);
#pragma unroll
                for (int mt = 0; mt < 2; mt++)
                    mma_tf32(acc[mt][nt], afr[mt], b0, b1);
            }
        }
        if (s < 15) {
            __syncthreads();
            sts_stage((s + 1) & 1);
            __syncthreads();
        }
    }

#pragma unroll
    for (int mt = 0; mt < 2; mt++)
#pragma unroll
        for (int nt = 0; nt < 8; nt++) {
            const int ra = wr * 32 + mt * 16 + r0;
            const int cb = wc * 64 + nt * 8 + c0 * 2;
            *(float2*)&g_h[(size_t)(m0 + ra) * OUTD + n0 + cb] =
                make_float2(acc[mt][nt][0], acc[mt][nt][1]);
            *(float2*)&g_h[(size_t)(m0 + ra + 8) * OUTD + n0 + cb] =
                make_float2(acc[mt][nt][2], acc[mt][nt][3]);
        }
}

// ---------------------------------------------------------------------------
// Kernel 2: as/an row dots; round H to tf32 (RNA) in place.
// ---------------------------------------------------------------------------
__global__ __launch_bounds__(256) void k2_attvec(const float* __restrict__ a_self,
                                                 const float* __restrict__ a_neighs) {
    const int warp = threadIdx.x >> 5, lane = threadIdx.x & 31;
    const int row = blockIdx.x * 8 + warp;
    float4* h4 = (float4*)&g_h[(size_t)row * OUTD];
    float s1 = 0.f, s2 = 0.f;
#pragma unroll
    for (int q = 0; q < 2; q++) {
        float4 v = h4[lane + 32 * q];
        float4 a = ((const float4*)a_self)[lane + 32 * q];
        float4 b = ((const float4*)a_neighs)[lane + 32 * q];
        s1 += v.x * a.x + v.y * a.y + v.z * a.z + v.w * a.w;
        s2 += v.x * b.x + v.y * b.y + v.z * b.z + v.w * b.w;
        float4 t;
        t.x = to_tf32(v.x); t.y = to_tf32(v.y);
        t.z = to_tf32(v.z); t.w = to_tf32(v.w);
        h4[lane + 32 * q] = t;
    }
#pragma unroll
    for (int off = 16; off >= 1; off >>= 1) {
        s1 += __shfl_xor_sync(0xffffffffu, s1, off);
        s2 += __shfl_xor_sync(0xffffffffu, s2, off);
    }
    if (lane == 0) { g_as[row] = s1; g_an[row] = s2; }
}

// ---------------------------------------------------------------------------
// Kernel 3: fused masked-exp attention GEMM.
// 64 rows x 256 cols per CTA, 128 k-tiles of 64. One barrier per tile.
// smem: sH[2][64*264] + sP[2][64*68] + as/rs = 170496 B dynamic.
// ---------------------------------------------------------------------------
#define K3_SMEM_FLOATS (2 * 16896 + 2 * 4352 + 64 + 64)
#define K3_SMEM_BYTES  (K3_SMEM_FLOATS * 4)

__global__ __launch_bounds__(256) void k3_attn(const float* __restrict__ Adj,
                                               const float* __restrict__ Mg,
                                               float* __restrict__ Out) {
    extern __shared__ float sm[];
    float* sH   = sm;                       // 2 x 64 x 264
    float* sP   = sm + 2 * 16896;           // 2 x 64 x 68
    float* s_as = sm + 2 * 16896 + 2 * 4352;
    float* s_rs = s_as + 64;

    const int tid = threadIdx.x;
    const int lane = tid & 31, warp = tid >> 5;
    const int rowbase = blockIdx.x * 64;
    const int r0 = lane >> 2, c0 = lane & 3;

    // P-compute mapping: 16 col-threads x 16 row-groups, 4 rows each
    const int g = tid >> 4, cbase = (tid & 15) << 2;

    // ldmatrix lane addressing (A-frag from sP)
    const int sel = lane >> 3, mrow = lane & 7;
    const int lrow = ((sel & 1) << 3) + mrow, lcol = (sel >> 1) << 2;
    const int lanepartP = lrow * 68 + lcol;
    const unsigned sP_u = (unsigned)__cvta_generic_to_shared(sP);

    if (tid < 16)
        *(float4*)&s_as[tid * 4] = *(const float4*)&g_as[rowbase + tid * 4];

    auto stageH = [&](int tt) {
        const int b = tt & 1;
        const int jb = tt * 64;
#pragma unroll
        for (int p = 0; p < 16; p++) {
            int ch = tid + p * 256;
            int r = ch >> 6, c = (ch & 63) << 2;
            cp16(&sH[b * 16896 + r * 264 + c], &g_h[(size_t)(jb + r) * OUTD + c]);
        }
        asm volatile("cp.async.commit_group;\n" ::: "memory");
    };

    float4 mreg[4], areg[4], an4;
    auto ldgMA = [&](int tt) {
        const int jb = tt * 64;
        an4 = *(const float4*)&g_an[jb + cbase];
#pragma unroll
        for (int it = 0; it < 4; it++) {
            size_t goff = (size_t)(rowbase + g + (it << 4)) * NROWS + jb + cbase;
            mreg[it] = __ldg((const float4*)&Mg[goff]);
            areg[it] = __ldg((const float4*)&Adj[goff]);
        }
    };

    float rsum[4] = {0.f, 0.f, 0.f, 0.f};

    auto computeP = [&](int tt) {
        const int b = tt & 1;
#pragma unroll
        for (int it = 0; it < 4; it++) {
            const int r = g + (it << 4);
            const float asr = s_as[r];
            float4 m4 = mreg[it], a4 = areg[it];
            float t0 = (asr + an4.x) * m4.x; t0 = t0 > 0.f ? t0 : 0.2f * t0;
            float t1 = (asr + an4.y) * m4.y; t1 = t1 > 0.f ? t1 : 0.2f * t1;
            float t2 = (asr + an4.z) * m4.z; t2 = t2 > 0.f ? t2 : 0.2f * t2;
            float t3 = (asr + an4.w) * m4.w; t3 = t3 > 0.f ? t3 : 0.2f * t3;
            float p0 = a4.x > 0.f ? __expf(t0) : 0.f;
            float p1 = a4.y > 0.f ? __expf(t1) : 0.f;
            float p2 = a4.z > 0.f ? __expf(t2) : 0.f;
            float p3 = a4.w > 0.f ? __expf(t3) : 0.f;
            rsum[it] += (p0 + p1) + (p2 + p3);
            *(float4*)&sP[b * 4352 + r * 68 + cbase] =
                make_float4(to_tf32(p0), to_tf32(p1), to_tf32(p2), to_tf32(p3));
        }
    };

    float acc[4][4][4] = {};

    // ---- prologue ----
    stageH(0);
    ldgMA(0);
    __syncthreads();        // s_as visible
    computeP(0);            // writes sP[0]
    asm volatile("cp.async.wait_group 0;\n" ::: "memory");
    __syncthreads();

    // ---- main loop: one barrier per tile ----
    for (int t = 0; t < 128; t++) {
        if (t < 127) { stageH(t + 1); ldgMA(t + 1); }

        // mma(t): reads sP[t&1], sH[t&1]
        {
            const int b = t & 1;
            const int nb = warp * 32;
#pragma unroll
            for (int k8 = 0; k8 < 8; k8++) {
                const int kb = k8 << 3;
                unsigned afr[4][4];
#pragma unroll
                for (int mt = 0; mt < 4; mt++)
                    ldsm4(afr[mt], sP_u + (b * 4352 + mt * 16 * 68 + kb + lanepartP) * 4u);
                const float* hp = &sH[b * 16896 + (kb + c0) * 264 + nb + r0];
#pragma unroll
                for (int nt = 0; nt < 4; nt++) {
                    unsigned b0 = __float_as_uint(hp[nt * 8]);
                    unsigned b1 = __float_as_uint(hp[4 * 264 + nt * 8]);
#pragma unroll
                    for (int mt = 0; mt < 4; mt++)
                        mma_tf32(acc[mt][nt], afr[mt], b0, b1);
                }
            }
        }

        if (t < 127) computeP(t + 1);   // writes sP[(t+1)&1] — overlaps HMMA drain
        asm volatile("cp.async.wait_group 0;\n" ::: "memory");
        __syncthreads();
    }

    // ---- rowsum reduction (16 threads per row) ----
#pragma unroll
    for (int off = 8; off >= 1; off >>= 1)
#pragma unroll
        for (int it = 0; it < 4; it++)
            rsum[it] += __shfl_xor_sync(0xffffffffu, rsum[it], off);
    if ((lane & 15) == 0) {
#pragma unroll
        for (int it = 0; it < 4; it++) s_rs[g + (it << 4)] = rsum[it];
    }
    __syncthreads();

    // ---- epilogue: divide, elu, store ----
#pragma unroll
    for (int mt = 0; mt < 4; mt++) {
        const int ra = mt * 16 + r0;
        const float ia = 1.0f / s_rs[ra];
        const float ib = 1.0f / s_rs[ra + 8];
#pragma unroll
        for (int nt = 0; nt < 4; nt++) {
            const int col = warp * 32 + nt * 8 + c0 * 2;
            float2 va = make_float2(elu_f(acc[mt][nt][0] * ia),
                                    elu_f(acc[mt][nt][1] * ia));
            float2 vb = make_float2(elu_f(acc[mt][nt][2] * ib),
                                    elu_f(acc[mt][nt][3] * ib));
            *(float2*)&Out[(size_t)(rowbase + ra) * OUTD + col] = va;
            *(float2*)&Out[(size_t)(rowbase + ra + 8) * OUTD + col] = vb;
        }
    }
}

// ---------------------------------------------------------------------------
extern "C" void kernel_launch(void* const* d_in, const int* in_sizes, int n_in,
                              void* d_out, int out_size) {
    const float* X        = (const float*)d_in[0];
    const float* Adj      = (const float*)d_in[1];
    const float* Mg       = (const float*)d_in[2];
    const float* W        = (const float*)d_in[3];
    const float* a_self   = (const float*)d_in[4];
    const float* a_neighs = (const float*)d_in[5];
    float* Out = (float*)d_out;

    cudaFuncSetAttribute(k1_gemm_xw, cudaFuncAttributeMaxDynamicSharedMemorySize,
                         K1_SMEM_BYTES);
    cudaFuncSetAttribute(k3_attn, cudaFuncAttributeMaxDynamicSharedMemorySize,
                         K3_SMEM_BYTES);

    k1_gemm_xw<<<dim3(2, 64), 256, K1_SMEM_BYTES>>>(X, W);
    k2_attvec<<<1024, 256>>>(a_self, a_neighs);
    k3_attn<<<128, 256, K3_SMEM_BYTES>>>(Adj, Mg, Out);
}

// round 8
// speedup vs baseline: 1.3822x; 1.2514x over previous
#include <cuda_runtime.h>
#include <cuda_fp16.h>
#include <cstdint>

// ---------------------------------------------------------------------------
// GAT layer (sm_100 base target — no tcgen05; legacy mma.sync only):
//   k1: H = X @ W                      (tf32 mma.sync m16n8k8, 27us)
//   k2: as/an row dots (fp32); emit g_h16 = fp16 H in k-paired layout
//   k3: Out = elu( (P @ H) / rowsum(P) )  via fp16 mma.sync m16n8k16
//       P_ij = adj_ij>0 ? exp(leakyrelu((as_i+an_j)*M_ij)) : 0
//       P stored as fp16 scaled by 2^-6 (range safety); rowsum fp32.
// ---------------------------------------------------------------------------

#define NROWS 8192
#define IND   512
#define OUTD  256

__device__ __align__(16) float  g_h  [NROWS * OUTD];
__device__ __align__(16) __half g_h16[NROWS * OUTD];   // word[jpair*256+n] = {h[2j][n], h[2j+1][n]}
__device__ __align__(16) float  g_as [NROWS];
__device__ __align__(16) float  g_an [NROWS];

#define PSCALE 0.015625f   // 2^-6

// ---------------------------------------------------------------------------
__device__ __forceinline__ float to_tf32(float x) {
    unsigned r;
    asm("cvt.rna.tf32.f32 %0, %1;\n" : "=r"(r) : "f"(x));
    return __uint_as_float(r);
}
__device__ __forceinline__ void mma_tf32(float* d, const unsigned* a,
                                         unsigned b0, unsigned b1) {
    asm volatile(
        "mma.sync.aligned.m16n8k8.row.col.f32.tf32.tf32.f32 "
        "{%0,%1,%2,%3}, {%4,%5,%6,%7}, {%8,%9}, {%0,%1,%2,%3};\n"
        : "+f"(d[0]), "+f"(d[1]), "+f"(d[2]), "+f"(d[3])
        : "r"(a[0]), "r"(a[1]), "r"(a[2]), "r"(a[3]), "r"(b0), "r"(b1));
}
__device__ __forceinline__ void mma_f16(float* d, const unsigned* a,
                                        unsigned b0, unsigned b1) {
    asm volatile(
        "mma.sync.aligned.m16n8k16.row.col.f32.f16.f16.f32 "
        "{%0,%1,%2,%3}, {%4,%5,%6,%7}, {%8,%9}, {%0,%1,%2,%3};\n"
        : "+f"(d[0]), "+f"(d[1]), "+f"(d[2]), "+f"(d[3])
        : "r"(a[0]), "r"(a[1]), "r"(a[2]), "r"(a[3]), "r"(b0), "r"(b1));
}
__device__ __forceinline__ void ldsm4(unsigned* a, unsigned addr) {
    asm volatile(
        "ldmatrix.sync.aligned.m8n8.x4.shared.b16 {%0,%1,%2,%3}, [%4];\n"
        : "=r"(a[0]), "=r"(a[1]), "=r"(a[2]), "=r"(a[3]) : "r"(addr));
}
__device__ __forceinline__ void cp16(void* smem, const void* g) {
    unsigned s = (unsigned)__cvta_generic_to_shared(smem);
    asm volatile("cp.async.cg.shared.global [%0], [%1], 16;\n" :: "r"(s), "l"(g));
}
__device__ __forceinline__ float elu_f(float x) { return x > 0.f ? x : expm1f(x); }

// ---------------------------------------------------------------------------
// Kernel 1: H = X @ W, tf32 mma.sync (R6-proven, 27us). grid (2, 64).
// ---------------------------------------------------------------------------
#define K1_SMEM_BYTES ((2 * 128 * 36 + 2 * 32 * 136) * 4)

__global__ __launch_bounds__(256) void k1_gemm_xw(const float* __restrict__ X,
                                                  const float* __restrict__ W) {
    extern __shared__ float sm1[];
    float* sX = sm1;
    float* sW = sm1 + 2 * 128 * 36;

    const int tid = threadIdx.x;
    const int lane = tid & 31, warp = tid >> 5;
    const int wr = warp & 3, wc = warp >> 2;
    const int m0 = blockIdx.y * 128, n0 = blockIdx.x * 128;
    const int r0 = lane >> 2, c0 = lane & 3;
    const int sel = lane >> 3, mrow = lane & 7;
    const int lrow = ((sel & 1) << 3) + mrow, lcol = (sel >> 1) << 2;
    const unsigned sX_u = (unsigned)__cvta_generic_to_shared(sX);

    float acc[2][8][4] = {};
    float4 xv[4], wv[4];

    auto ldg_stage = [&](int k0) {
#pragma unroll
        for (int p = 0; p < 4; p++) {
            int q = tid + p * 256;
            xv[p] = *(const float4*)&X[(size_t)(m0 + (q >> 3)) * IND + k0 + ((q & 7) << 2)];
            wv[p] = *(const float4*)&W[(size_t)(k0 + (q >> 5)) * OUTD + n0 + ((q & 31) << 2)];
        }
    };
    auto sts_stage = [&](int buf) {
#pragma unroll
        for (int p = 0; p < 4; p++) {
            int q = tid + p * 256;
            float4 t = make_float4(to_tf32(xv[p].x), to_tf32(xv[p].y),
                                   to_tf32(xv[p].z), to_tf32(xv[p].w));
            *(float4*)&sX[buf * 4608 + (q >> 3) * 36 + ((q & 7) << 2)] = t;
            float4 u = make_float4(to_tf32(wv[p].x), to_tf32(wv[p].y),
                                   to_tf32(wv[p].z), to_tf32(wv[p].w));
            *(float4*)&sW[buf * 4352 + (q >> 5) * 136 + ((q & 31) << 2)] = u;
        }
    };

    ldg_stage(0);
    sts_stage(0);
    __syncthreads();

    for (int s = 0; s < 16; s++) {
        const int buf = s & 1;
        if (s < 15) ldg_stage((s + 1) * 32);
#pragma unroll
        for (int k8 = 0; k8 < 4; k8++) {
            const int kb = k8 << 3;
            unsigned afr[2][4];
#pragma unroll
            for (int mt = 0; mt < 2; mt++) {
                unsigned addr = sX_u +
                    (buf * 4608 + (wr * 32 + mt * 16 + lrow) * 36 + kb + lcol) * 4u;
                ldsm4(afr[mt], addr);
            }
            const float* wp = &sW[buf * 4352 + (kb + c0) * 136 + wc * 64 + r0];
#pragma unroll
            for (int nt = 0; nt < 8; nt++) {
                unsigned b0 = __float_as_uint(wp[nt * 8]);
                unsigned b1 = __float_as_uint(wp[4 * 136 + nt * 8]);
#pragma unroll
                for (int mt = 0; mt < 2; mt++)
                    mma_tf32(acc[mt][nt], afr[mt], b0, b1);
            }
        }
        if (s < 15) {
            __syncthreads();
            sts_stage((s + 1) & 1);
            __syncthreads();
        }
    }
#pragma unroll
    for (int mt = 0; mt < 2; mt++)
#pragma unroll
        for (int nt = 0; nt < 8; nt++) {
            const int ra = wr * 32 + mt * 16 + r0;
            const int cb = wc * 64 + nt * 8 + c0 * 2;
            *(float2*)&g_h[(size_t)(m0 + ra) * OUTD + n0 + cb] =
                make_float2(acc[mt][nt][0], acc[mt][nt][1]);
            *(float2*)&g_h[(size_t)(m0 + ra + 8) * OUTD + n0 + cb] =
                make_float2(acc[mt][nt][2], acc[mt][nt][3]);
        }
}

// ---------------------------------------------------------------------------
// Kernel 2: as/an row dots (fp32); write g_h16 (fp16, k-paired layout).
// ---------------------------------------------------------------------------
__global__ __launch_bounds__(256) void k2_attvec(const float* __restrict__ a_self,
                                                 const float* __restrict__ a_neighs) {
    const int warp = threadIdx.x >> 5, lane = threadIdx.x & 31;
    const int row = blockIdx.x * 8 + warp;
    const float4* h4 = (const float4*)&g_h[(size_t)row * OUTD];
    __half* dst = &g_h16[(size_t)(row >> 1) * 512 + (row & 1)];
    float s1 = 0.f, s2 = 0.f;
#pragma unroll
    for (int q = 0; q < 2; q++) {
        float4 v = h4[lane + 32 * q];
        float4 a = ((const float4*)a_self)[lane + 32 * q];
        float4 b = ((const float4*)a_neighs)[lane + 32 * q];
        s1 += v.x * a.x + v.y * a.y + v.z * a.z + v.w * a.w;
        s2 += v.x * b.x + v.y * b.y + v.z * b.z + v.w * b.w;
        const int c = (lane + 32 * q) * 4;
        dst[(c + 0) * 2] = __float2half_rn(v.x);
        dst[(c + 1) * 2] = __float2half_rn(v.y);
        dst[(c + 2) * 2] = __float2half_rn(v.z);
        dst[(c + 3) * 2] = __float2half_rn(v.w);
    }
#pragma unroll
    for (int off = 16; off >= 1; off >>= 1) {
        s1 += __shfl_xor_sync(0xffffffffu, s1, off);
        s2 += __shfl_xor_sync(0xffffffffu, s2, off);
    }
    if (lane == 0) { g_as[row] = s1; g_an[row] = s2; }
}

// ---------------------------------------------------------------------------
// Kernel 3: fused masked-exp attention GEMM, fp16 m16n8k16.
// 64 rows x 256 cols per CTA, 128 k-tiles of 64 j. grid 128, 256 thr.
// smem: sHu 2 x 32x260 u32 (66560B) + sP 2 x 64x72 half (18432B) + misc.
// ---------------------------------------------------------------------------
#define SHU_STRIDE 260
#define SHU_BUF    (32 * SHU_STRIDE)          // u32 per buffer
#define SP_HBUF    (64 * 72)                  // halves per buffer
#define SP_BYTE0   (2 * SHU_BUF * 4)          // 66560
#define SAS_F      ((SP_BYTE0 + 2 * SP_HBUF * 2) / 4)   // float idx 21248
#define SRS_F      (SAS_F + 64)
#define K3_SMEM_BYTES ((SRS_F + 64) * 4)

__global__ __launch_bounds__(256) void k3_attn(const float* __restrict__ Adj,
                                               const float* __restrict__ Mg,
                                               float* __restrict__ Out) {
    extern __shared__ float sm[];
    uint32_t* sHu = (uint32_t*)sm;                    // 2 buffers
    __half*   sPh = (__half*)((char*)sm + SP_BYTE0);  // 2 buffers
    float* s_as = sm + SAS_F;
    float* s_rs = sm + SRS_F;

    const int tid = threadIdx.x;
    const int lane = tid & 31, warp = tid >> 5;
    const int rowbase = blockIdx.x * 64;
    const int r0 = lane >> 2, c0 = lane & 3;
    const int g = tid >> 4, cbase = (tid & 15) << 2;
    const unsigned sP_u = (unsigned)__cvta_generic_to_shared(sPh);

    if (tid < 16)
        *(float4*)&s_as[tid * 4] = *(const float4*)&g_as[rowbase + tid * 4];

    auto stageH = [&](int tt) {
        const int b = tt & 1;
        const char* src = (const char*)g_h16 + (size_t)tt * 32 * 1024;
#pragma unroll
        for (int p = 0; p < 8; p++) {
            int ch = tid + p * 256;
            int pr = ch >> 6, c = ch & 63;
            cp16(&sHu[b * SHU_BUF + pr * SHU_STRIDE + c * 4],
                 src + (size_t)pr * 1024 + c * 16);
        }
        asm volatile("cp.async.commit_group;\n" ::: "memory");
    };

    float4 mreg[4], areg[4], an4;
    auto ldgMA = [&](int tt) {
        const int jb = tt * 64;
        an4 = *(const float4*)&g_an[jb + cbase];
#pragma unroll
        for (int it = 0; it < 4; it++) {
            size_t goff = (size_t)(rowbase + g + (it << 4)) * NROWS + jb + cbase;
            mreg[it] = __ldg((const float4*)&Mg[goff]);
            areg[it] = __ldg((const float4*)&Adj[goff]);
        }
    };

    float rsum[4] = {0.f, 0.f, 0.f, 0.f};

    auto computeP = [&](int tt) {
        const int b = tt & 1;
#pragma unroll
        for (int it = 0; it < 4; it++) {
            const int r = g + (it << 4);
            const float asr = s_as[r];
            float4 m4 = mreg[it], a4 = areg[it];
            float t0 = (asr + an4.x) * m4.x; t0 = t0 > 0.f ? t0 : 0.2f * t0;
            float t1 = (asr + an4.y) * m4.y; t1 = t1 > 0.f ? t1 : 0.2f * t1;
            float t2 = (asr + an4.z) * m4.z; t2 = t2 > 0.f ? t2 : 0.2f * t2;
            float t3 = (asr + an4.w) * m4.w; t3 = t3 > 0.f ? t3 : 0.2f * t3;
            float p0 = a4.x > 0.f ? __expf(t0) : 0.f;
            float p1 = a4.y > 0.f ? __expf(t1) : 0.f;
            float p2 = a4.z > 0.f ? __expf(t2) : 0.f;
            float p3 = a4.w > 0.f ? __expf(t3) : 0.f;
            rsum[it] += (p0 + p1) + (p2 + p3);
            __half2 h01 = __floats2half2_rn(p0 * PSCALE, p1 * PSCALE);
            __half2 h23 = __floats2half2_rn(p2 * PSCALE, p3 * PSCALE);
            *(uint2*)&sPh[b * SP_HBUF + r * 72 + cbase] =
                make_uint2(*(unsigned*)&h01, *(unsigned*)&h23);
        }
    };

    float acc[4][4][4] = {};

    // ---- prologue ----
    stageH(0);
    ldgMA(0);
    __syncthreads();                 // s_as visible
    computeP(0);
    asm volatile("cp.async.wait_group 0;\n" ::: "memory");
    __syncthreads();

    // ---- main loop ----
    for (int t = 0; t < 128; t++) {
        const int b = t & 1;
        if (t < 127) { stageH(t + 1); ldgMA(t + 1); }

        // mma(t): fp16 m16n8k16, 4 k-chunks of 16
        {
            const int nb = warp * 32 + r0;
#pragma unroll
            for (int c16 = 0; c16 < 4; c16++) {
                unsigned afr[4][4];
#pragma unroll
                for (int mt = 0; mt < 4; mt++) {
                    unsigned addr = sP_u +
                        (b * SP_HBUF + (mt * 16 + (lane & 15)) * 72 +
                         c16 * 16 + (lane >> 4) * 8) * 2u;
                    ldsm4(afr[mt], addr);
                }
                const uint32_t* hp =
                    &sHu[b * SHU_BUF + (c16 * 8 + c0) * SHU_STRIDE + nb];
#pragma unroll
                for (int nt = 0; nt < 4; nt++) {
                    unsigned b0 = hp[nt * 8];
                    unsigned b1 = hp[4 * SHU_STRIDE + nt * 8];
#pragma unroll
                    for (int mt = 0; mt < 4; mt++)
                        mma_f16(acc[mt][nt], afr[mt], b0, b1);
                }
            }
        }

        if (t < 127) computeP(t + 1);
        asm volatile("cp.async.wait_group 0;\n" ::: "memory");
        __syncthreads();
    }

    // ---- rowsum reduction (16 threads per row) ----
#pragma unroll
    for (int off = 8; off >= 1; off >>= 1)
#pragma unroll
        for (int it = 0; it < 4; it++)
            rsum[it] += __shfl_xor_sync(0xffffffffu, rsum[it], off);
    if ((lane & 15) == 0) {
#pragma unroll
        for (int it = 0; it < 4; it++) s_rs[g + (it << 4)] = rsum[it];
    }
    __syncthreads();

    // ---- epilogue: divide (undo 2^-6 scale), elu, store ----
#pragma unroll
    for (int mt = 0; mt < 4; mt++) {
        const int ra = mt * 16 + r0;
        const float ia = 64.0f / s_rs[ra];
        const float ib = 64.0f / s_rs[ra + 8];
#pragma unroll
        for (int nt = 0; nt < 4; nt++) {
            const int col = warp * 32 + nt * 8 + c0 * 2;
            float2 va = make_float2(elu_f(acc[mt][nt][0] * ia),
                                    elu_f(acc[mt][nt][1] * ia));
            float2 vb = make_float2(elu_f(acc[mt][nt][2] * ib),
                                    elu_f(acc[mt][nt][3] * ib));
            *(float2*)&Out[(size_t)(rowbase + ra) * OUTD + col] = va;
            *(float2*)&Out[(size_t)(rowbase + ra + 8) * OUTD + col] = vb;
        }
    }
}

// ---------------------------------------------------------------------------
extern "C" void kernel_launch(void* const* d_in, const int* in_sizes, int n_in,
                              void* d_out, int out_size) {
    const float* X        = (const float*)d_in[0];
    const float* Adj      = (const float*)d_in[1];
    const float* Mg       = (const float*)d_in[2];
    const float* W        = (const float*)d_in[3];
    const float* a_self   = (const float*)d_in[4];
    const float* a_neighs = (const float*)d_in[5];
    float* Out = (float*)d_out;

    cudaFuncSetAttribute(k1_gemm_xw, cudaFuncAttributeMaxDynamicSharedMemorySize,
                         K1_SMEM_BYTES);
    cudaFuncSetAttribute(k3_attn, cudaFuncAttributeMaxDynamicSharedMemorySize,
                         K3_SMEM_BYTES);

    k1_gemm_xw<<<dim3(2, 64), 256, K1_SMEM_BYTES>>>(X, W);
    k2_attvec<<<1024, 256>>>(a_self, a_neighs);
    k3_attn<<<128, 256, K3_SMEM_BYTES>>>(Adj, Mg, Out);
}

// round 9
// speedup vs baseline: 1.4361x; 1.0390x over previous
#include <cuda_runtime.h>
#include <cuda_fp16.h>
#include <cstdint>

// ---------------------------------------------------------------------------
// GAT layer (sm_100 base target — legacy mma.sync only):
//   k1: H = X @ W                      (tf32 mma.sync m16n8k8, 27us)
//   k2: as/an row dots (fp32); emit g_h16 = fp16 H in k-paired layout
//   k3: Out = elu( (P @ H) / rowsum(P) )  via fp16 mma.sync m16n8k16
//       P_ij = adj_ij>0 ? exp(leakyrelu((as_i+an_j)*M_ij)) : 0
//       P fp16 scaled 2^-6; rowsum fp32. JT=128 k-tiles (64 iters).
// ---------------------------------------------------------------------------

#define NROWS 8192
#define IND   512
#define OUTD  256
#define JT    128
#define NTILE (NROWS / JT)     // 64

__device__ __align__(16) float  g_h  [NROWS * OUTD];
__device__ __align__(16) __half g_h16[NROWS * OUTD];   // word[jpair*256+n] = {h[2j][n], h[2j+1][n]}
__device__ __align__(16) float  g_as [NROWS];
__device__ __align__(16) float  g_an [NROWS];

#define PSCALE 0.015625f   // 2^-6

// ---------------------------------------------------------------------------
__device__ __forceinline__ float to_tf32(float x) {
    unsigned r;
    asm("cvt.rna.tf32.f32 %0, %1;\n" : "=r"(r) : "f"(x));
    return __uint_as_float(r);
}
__device__ __forceinline__ void mma_tf32(float* d, const unsigned* a,
                                         unsigned b0, unsigned b1) {
    asm volatile(
        "mma.sync.aligned.m16n8k8.row.col.f32.tf32.tf32.f32 "
        "{%0,%1,%2,%3}, {%4,%5,%6,%7}, {%8,%9}, {%0,%1,%2,%3};\n"
        : "+f"(d[0]), "+f"(d[1]), "+f"(d[2]), "+f"(d[3])
        : "r"(a[0]), "r"(a[1]), "r"(a[2]), "r"(a[3]), "r"(b0), "r"(b1));
}
__device__ __forceinline__ void mma_f16(float* d, const unsigned* a,
                                        unsigned b0, unsigned b1) {
    asm volatile(
        "mma.sync.aligned.m16n8k16.row.col.f32.f16.f16.f32 "
        "{%0,%1,%2,%3}, {%4,%5,%6,%7}, {%8,%9}, {%0,%1,%2,%3};\n"
        : "+f"(d[0]), "+f"(d[1]), "+f"(d[2]), "+f"(d[3])
        : "r"(a[0]), "r"(a[1]), "r"(a[2]), "r"(a[3]), "r"(b0), "r"(b1));
}
__device__ __forceinline__ void ldsm4(unsigned* a, unsigned addr) {
    asm volatile(
        "ldmatrix.sync.aligned.m8n8.x4.shared.b16 {%0,%1,%2,%3}, [%4];\n"
        : "=r"(a[0]), "=r"(a[1]), "=r"(a[2]), "=r"(a[3]) : "r"(addr));
}
__device__ __forceinline__ void cp16(void* smem, const void* g) {
    unsigned s = (unsigned)__cvta_generic_to_shared(smem);
    asm volatile("cp.async.cg.shared.global [%0], [%1], 16;\n" :: "r"(s), "l"(g));
}
__device__ __forceinline__ float elu_f(float x) { return x > 0.f ? x : expm1f(x); }

// ---------------------------------------------------------------------------
// Kernel 1: H = X @ W, tf32 mma.sync (R6-proven, 27us). grid (2, 64).
// ---------------------------------------------------------------------------
#define K1_SMEM_BYTES ((2 * 128 * 36 + 2 * 32 * 136) * 4)

__global__ __launch_bounds__(256) void k1_gemm_xw(const float* __restrict__ X,
                                                  const float* __restrict__ W) {
    extern __shared__ float sm1[];
    float* sX = sm1;
    float* sW = sm1 + 2 * 128 * 36;

    const int tid = threadIdx.x;
    const int lane = tid & 31, warp = tid >> 5;
    const int wr = warp & 3, wc = warp >> 2;
    const int m0 = blockIdx.y * 128, n0 = blockIdx.x * 128;
    const int r0 = lane >> 2, c0 = lane & 3;
    const int sel = lane >> 3, mrow = lane & 7;
    const int lrow = ((sel & 1) << 3) + mrow, lcol = (sel >> 1) << 2;
    const unsigned sX_u = (unsigned)__cvta_generic_to_shared(sX);

    float acc[2][8][4] = {};
    float4 xv[4], wv[4];

    auto ldg_stage = [&](int k0) {
#pragma unroll
        for (int p = 0; p < 4; p++) {
            int q = tid + p * 256;
            xv[p] = *(const float4*)&X[(size_t)(m0 + (q >> 3)) * IND + k0 + ((q & 7) << 2)];
            wv[p] = *(const float4*)&W[(size_t)(k0 + (q >> 5)) * OUTD + n0 + ((q & 31) << 2)];
        }
    };
    auto sts_stage = [&](int buf) {
#pragma unroll
        for (int p = 0; p < 4; p++) {
            int q = tid + p * 256;
            float4 t = make_float4(to_tf32(xv[p].x), to_tf32(xv[p].y),
                                   to_tf32(xv[p].z), to_tf32(xv[p].w));
            *(float4*)&sX[buf * 4608 + (q >> 3) * 36 + ((q & 7) << 2)] = t;
            float4 u = make_float4(to_tf32(wv[p].x), to_tf32(wv[p].y),
                                   to_tf32(wv[p].z), to_tf32(wv[p].w));
            *(float4*)&sW[buf * 4352 + (q >> 5) * 136 + ((q & 31) << 2)] = u;
        }
    };

    ldg_stage(0);
    sts_stage(0);
    __syncthreads();

    for (int s = 0; s < 16; s++) {
        const int buf = s & 1;
        if (s < 15) ldg_stage((s + 1) * 32);
#pragma unroll
        for (int k8 = 0; k8 < 4; k8++) {
            const int kb = k8 << 3;
            unsigned afr[2][4];
#pragma unroll
            for (int mt = 0; mt < 2; mt++) {
                unsigned addr = sX_u +
                    (buf * 4608 + (wr * 32 + mt * 16 + lrow) * 36 + kb + lcol) * 4u;
                ldsm4(afr[mt], addr);
            }
            const float* wp = &sW[buf * 4352 + (kb + c0) * 136 + wc * 64 + r0];
#pragma unroll
            for (int nt = 0; nt < 8; nt++) {
                unsigned b0 = __float_as_uint(wp[nt * 8]);
                unsigned b1 = __float_as_uint(wp[4 * 136 + nt * 8]);
#pragma unroll
                for (int mt = 0; mt < 2; mt++)
                    mma_tf32(acc[mt][nt], afr[mt], b0, b1);
            }
        }
        if (s < 15) {
            __syncthreads();
            sts_stage((s + 1) & 1);
            __syncthreads();
        }
    }
#pragma unroll
    for (int mt = 0; mt < 2; mt++)
#pragma unroll
        for (int nt = 0; nt < 8; nt++) {
            const int ra = wr * 32 + mt * 16 + r0;
            const int cb = wc * 64 + nt * 8 + c0 * 2;
            *(float2*)&g_h[(size_t)(m0 + ra) * OUTD + n0 + cb] =
                make_float2(acc[mt][nt][0], acc[mt][nt][1]);
            *(float2*)&g_h[(size_t)(m0 + ra + 8) * OUTD + n0 + cb] =
                make_float2(acc[mt][nt][2], acc[mt][nt][3]);
        }
}

// ---------------------------------------------------------------------------
// Kernel 2: as/an row dots (fp32); write g_h16 (fp16, k-paired layout).
// ---------------------------------------------------------------------------
__global__ __launch_bounds__(256) void k2_attvec(const float* __restrict__ a_self,
                                                 const float* __restrict__ a_neighs) {
    const int warp = threadIdx.x >> 5, lane = threadIdx.x & 31;
    const int row = blockIdx.x * 8 + warp;
    const float4* h4 = (const float4*)&g_h[(size_t)row * OUTD];
    __half* dst = &g_h16[(size_t)(row >> 1) * 512 + (row & 1)];
    float s1 = 0.f, s2 = 0.f;
#pragma unroll
    for (int q = 0; q < 2; q++) {
        float4 v = h4[lane + 32 * q];
        float4 a = ((const float4*)a_self)[lane + 32 * q];
        float4 b = ((const float4*)a_neighs)[lane + 32 * q];
        s1 += v.x * a.x + v.y * a.y + v.z * a.z + v.w * a.w;
        s2 += v.x * b.x + v.y * b.y + v.z * b.z + v.w * b.w;
        const int c = (lane + 32 * q) * 4;
        dst[(c + 0) * 2] = __float2half_rn(v.x);
        dst[(c + 1) * 2] = __float2half_rn(v.y);
        dst[(c + 2) * 2] = __float2half_rn(v.z);
        dst[(c + 3) * 2] = __float2half_rn(v.w);
    }
#pragma unroll
    for (int off = 16; off >= 1; off >>= 1) {
        s1 += __shfl_xor_sync(0xffffffffu, s1, off);
        s2 += __shfl_xor_sync(0xffffffffu, s2, off);
    }
    if (lane == 0) { g_as[row] = s1; g_an[row] = s2; }
}

// ---------------------------------------------------------------------------
// Kernel 3: fused masked-exp attention GEMM, fp16 m16n8k16, JT=128.
// 64 rows x 256 cols per CTA, 64 k-tiles of 128 j. grid 128, 256 thr.
// smem: sHu 2 x 64x260 u32 (133120B) + sP 2 x 64x136 half (34816B) + misc.
// ---------------------------------------------------------------------------
#define SHU_STRIDE 260
#define SHU_BUF    (64 * SHU_STRIDE)          // u32 per buffer
#define SP_STRIDE  136                        // halves per row
#define SP_HBUF    (64 * SP_STRIDE)           // halves per buffer
#define SP_BYTE0   (2 * SHU_BUF * 4)          // 133120
#define SAS_F      ((SP_BYTE0 + 2 * SP_HBUF * 2) / 4)   // float idx 41984
#define SRS_F      (SAS_F + 64)
#define K3_SMEM_BYTES ((SRS_F + 64) * 4)

__global__ __launch_bounds__(256) void k3_attn(const float* __restrict__ Adj,
                                               const float* __restrict__ Mg,
                                               float* __restrict__ Out) {
    extern __shared__ float sm[];
    uint32_t* sHu = (uint32_t*)sm;                    // 2 buffers
    __half*   sPh = (__half*)((char*)sm + SP_BYTE0);  // 2 buffers
    float* s_as = sm + SAS_F;
    float* s_rs = sm + SRS_F;

    const int tid = threadIdx.x;
    const int lane = tid & 31, warp = tid >> 5;
    const int rowbase = blockIdx.x * 64;
    const int r0 = lane >> 2, c0 = lane & 3;
    const int g = tid >> 4, cbase = (tid & 15) << 3;   // 8 cols per thread
    const unsigned sP_u = (unsigned)__cvta_generic_to_shared(sPh);

    if (tid < 16)
        *(float4*)&s_as[tid * 4] = *(const float4*)&g_as[rowbase + tid * 4];

    auto stageH = [&](int tt) {
        const int b = tt & 1;
        const char* src = (const char*)g_h16 + (size_t)tt * 64 * 1024;
#pragma unroll
        for (int p = 0; p < 16; p++) {
            int ch = tid + p * 256;
            int pr = ch >> 6, c = ch & 63;
            cp16(&sHu[b * SHU_BUF + pr * SHU_STRIDE + c * 4],
                 src + (size_t)pr * 1024 + c * 16);
        }
        asm volatile("cp.async.commit_group;\n" ::: "memory");
    };

    float4 mreg[4][2], areg[4][2], ana, anb;
    auto ldgMA = [&](int tt) {
        const int jb = tt * JT;
        ana = *(const float4*)&g_an[jb + cbase];
        anb = *(const float4*)&g_an[jb + cbase + 4];
#pragma unroll
        for (int it = 0; it < 4; it++) {
            size_t goff = (size_t)(rowbase + g + (it << 4)) * NROWS + jb + cbase;
            mreg[it][0] = __ldg((const float4*)&Mg[goff]);
            mreg[it][1] = __ldg((const float4*)&Mg[goff + 4]);
            areg[it][0] = __ldg((const float4*)&Adj[goff]);
            areg[it][1] = __ldg((const float4*)&Adj[goff + 4]);
        }
    };

    float rsum[4] = {0.f, 0.f, 0.f, 0.f};

    auto computeP = [&](int tt) {
        const int b = tt & 1;
#pragma unroll
        for (int it = 0; it < 4; it++) {
            const int r = g + (it << 4);
            const float asr = s_as[r];
            float p[8];
#pragma unroll
            for (int hh = 0; hh < 2; hh++) {
                float4 m4 = mreg[it][hh], a4 = areg[it][hh];
                float4 an = hh ? anb : ana;
                float t0 = (asr + an.x) * m4.x; t0 = t0 > 0.f ? t0 : 0.2f * t0;
                float t1 = (asr + an.y) * m4.y; t1 = t1 > 0.f ? t1 : 0.2f * t1;
                float t2 = (asr + an.z) * m4.z; t2 = t2 > 0.f ? t2 : 0.2f * t2;
                float t3 = (asr + an.w) * m4.w; t3 = t3 > 0.f ? t3 : 0.2f * t3;
                p[hh * 4 + 0] = a4.x > 0.f ? __expf(t0) : 0.f;
                p[hh * 4 + 1] = a4.y > 0.f ? __expf(t1) : 0.f;
                p[hh * 4 + 2] = a4.z > 0.f ? __expf(t2) : 0.f;
                p[hh * 4 + 3] = a4.w > 0.f ? __expf(t3) : 0.f;
            }
            rsum[it] += ((p[0] + p[1]) + (p[2] + p[3])) +
                        ((p[4] + p[5]) + (p[6] + p[7]));
            __half2 h01 = __floats2half2_rn(p[0] * PSCALE, p[1] * PSCALE);
            __half2 h23 = __floats2half2_rn(p[2] * PSCALE, p[3] * PSCALE);
            __half2 h45 = __floats2half2_rn(p[4] * PSCALE, p[5] * PSCALE);
            __half2 h67 = __floats2half2_rn(p[6] * PSCALE, p[7] * PSCALE);
            *(uint4*)&sPh[b * SP_HBUF + r * SP_STRIDE + cbase] =
                make_uint4(*(unsigned*)&h01, *(unsigned*)&h23,
                           *(unsigned*)&h45, *(unsigned*)&h67);
        }
    };

    float acc[4][4][4] = {};

    // ---- prologue ----
    stageH(0);
    ldgMA(0);
    __syncthreads();                 // s_as visible
    computeP(0);
    asm volatile("cp.async.wait_group 0;\n" ::: "memory");
    __syncthreads();

    // ---- main loop: 64 iterations ----
    for (int t = 0; t < NTILE; t++) {
        const int b = t & 1;
        if (t < NTILE - 1) { stageH(t + 1); ldgMA(t + 1); }

        // mma(t): fp16 m16n8k16, 8 k-chunks of 16
        {
            const int nb = warp * 32 + r0;
#pragma unroll
            for (int c16 = 0; c16 < 8; c16++) {
                unsigned afr[4][4];
#pragma unroll
                for (int mt = 0; mt < 4; mt++) {
                    unsigned addr = sP_u +
                        (b * SP_HBUF + (mt * 16 + (lane & 15)) * SP_STRIDE +
                         c16 * 16 + (lane >> 4) * 8) * 2u;
                    ldsm4(afr[mt], addr);
                }
                const uint32_t* hp =
                    &sHu[b * SHU_BUF + (c16 * 8 + c0) * SHU_STRIDE + nb];
#pragma unroll
                for (int nt = 0; nt < 4; nt++) {
                    unsigned b0 = hp[nt * 8];
                    unsigned b1 = hp[4 * SHU_STRIDE + nt * 8];
#pragma unroll
                    for (int mt = 0; mt < 4; mt++)
                        mma_f16(acc[mt][nt], afr[mt], b0, b1);
                }
            }
        }

        if (t < NTILE - 1) computeP(t + 1);
        asm volatile("cp.async.wait_group 0;\n" ::: "memory");
        __syncthreads();
    }

    // ---- rowsum reduction (16 threads per row) ----
#pragma unroll
    for (int off = 8; off >= 1; off >>= 1)
#pragma unroll
        for (int it = 0; it < 4; it++)
            rsum[it] += __shfl_xor_sync(0xffffffffu, rsum[it], off);
    if ((lane & 15) == 0) {
#pragma unroll
        for (int it = 0; it < 4; it++) s_rs[g + (it << 4)] = rsum[it];
    }
    __syncthreads();

    // ---- epilogue: divide (undo 2^-6 scale), elu, store ----
#pragma unroll
    for (int mt = 0; mt < 4; mt++) {
        const int ra = mt * 16 + r0;
        const float ia = 64.0f / s_rs[ra];
        const float ib = 64.0f / s_rs[ra + 8];
#pragma unroll
        for (int nt = 0; nt < 4; nt++) {
            const int col = warp * 32 + nt * 8 + c0 * 2;
            float2 va = make_float2(elu_f(acc[mt][nt][0] * ia),
                                    elu_f(acc[mt][nt][1] * ia));
            float2 vb = make_float2(elu_f(acc[mt][nt][2] * ib),
                                    elu_f(acc[mt][nt][3] * ib));
            *(float2*)&Out[(size_t)(rowbase + ra) * OUTD + col] = va;
            *(float2*)&Out[(size_t)(rowbase + ra + 8) * OUTD + col] = vb;
        }
    }
}

// ---------------------------------------------------------------------------
extern "C" void kernel_launch(void* const* d_in, const int* in_sizes, int n_in,
                              void* d_out, int out_size) {
    const float* X        = (const float*)d_in[0];
    const float* Adj      = (const float*)d_in[1];
    const float* Mg       = (const float*)d_in[2];
    const float* W        = (const float*)d_in[3];
    const float* a_self   = (const float*)d_in[4];
    const float* a_neighs = (const float*)d_in[5];
    float* Out = (float*)d_out;

    cudaFuncSetAttribute(k1_gemm_xw, cudaFuncAttributeMaxDynamicSharedMemorySize,
                         K1_SMEM_BYTES);
    cudaFuncSetAttribute(k3_attn, cudaFuncAttributeMaxDynamicSharedMemorySize,
                         K3_SMEM_BYTES);

    k1_gemm_xw<<<dim3(2, 64), 256, K1_SMEM_BYTES>>>(X, W);
    k2_attvec<<<1024, 256>>>(a_self, a_neighs);
    k3_attn<<<128, 256, K3_SMEM_BYTES>>>(Adj, Mg, Out);
}

// round 10
// speedup vs baseline: 1.5751x; 1.0967x over previous
#include <cuda_runtime.h>
#include <cuda_fp16.h>
#include <cstdint>

// ---------------------------------------------------------------------------
// GAT layer (sm_100 base target — legacy mma.sync only):
//   k1: H = X @ W                      (tf32 mma.sync m16n8k8, 27us)
//   k2: as/an row dots (fp32); emit g_h16 = fp16 H in k-paired layout
//   k3: Out = elu( (P @ H) / rowsum(P) )  via fp16 mma.sync m16n8k16
//       *** fp16 ACCUMULATE per k-tile, promoted to fp32 masters per tile ***
//       P fp16 scaled 2^-6; rowsum fp32. JT=128 (64 iters); computeP
//       interleaved into the mma chunk stream.
// ---------------------------------------------------------------------------

#define NROWS 8192
#define IND   512
#define OUTD  256
#define JT    128
#define NTILE (NROWS / JT)     // 64

__device__ __align__(16) float  g_h  [NROWS * OUTD];
__device__ __align__(16) __half g_h16[NROWS * OUTD];   // word[jpair*256+n] = {h[2j][n], h[2j+1][n]}
__device__ __align__(16) float  g_as [NROWS];
__device__ __align__(16) float  g_an [NROWS];

#define PSCALE 0.015625f   // 2^-6

// ---------------------------------------------------------------------------
__device__ __forceinline__ float to_tf32(float x) {
    unsigned r;
    asm("cvt.rna.tf32.f32 %0, %1;\n" : "=r"(r) : "f"(x));
    return __uint_as_float(r);
}
__device__ __forceinline__ void mma_tf32(float* d, const unsigned* a,
                                         unsigned b0, unsigned b1) {
    asm volatile(
        "mma.sync.aligned.m16n8k8.row.col.f32.tf32.tf32.f32 "
        "{%0,%1,%2,%3}, {%4,%5,%6,%7}, {%8,%9}, {%0,%1,%2,%3};\n"
        : "+f"(d[0]), "+f"(d[1]), "+f"(d[2]), "+f"(d[3])
        : "r"(a[0]), "r"(a[1]), "r"(a[2]), "r"(a[3]), "r"(b0), "r"(b1));
}
// fp16 accumulate variant: D,C are 2 x .f16x2 regs
__device__ __forceinline__ void mma_f16a(unsigned* d, const unsigned* a,
                                         unsigned b0, unsigned b1) {
    asm volatile(
        "mma.sync.aligned.m16n8k16.row.col.f16.f16.f16.f16 "
        "{%0,%1}, {%2,%3,%4,%5}, {%6,%7}, {%0,%1};\n"
        : "+r"(d[0]), "+r"(d[1])
        : "r"(a[0]), "r"(a[1]), "r"(a[2]), "r"(a[3]), "r"(b0), "r"(b1));
}
__device__ __forceinline__ void ldsm4(unsigned* a, unsigned addr) {
    asm volatile(
        "ldmatrix.sync.aligned.m8n8.x4.shared.b16 {%0,%1,%2,%3}, [%4];\n"
        : "=r"(a[0]), "=r"(a[1]), "=r"(a[2]), "=r"(a[3]) : "r"(addr));
}
__device__ __forceinline__ void cp16(void* smem, const void* g) {
    unsigned s = (unsigned)__cvta_generic_to_shared(smem);
    asm volatile("cp.async.cg.shared.global [%0], [%1], 16;\n" :: "r"(s), "l"(g));
}
__device__ __forceinline__ float elu_f(float x) { return x > 0.f ? x : expm1f(x); }

// ---------------------------------------------------------------------------
// Kernel 1: H = X @ W, tf32 mma.sync (R6-proven, 27us). grid (2, 64).
// ---------------------------------------------------------------------------
#define K1_SMEM_BYTES ((2 * 128 * 36 + 2 * 32 * 136) * 4)

__global__ __launch_bounds__(256) void k1_gemm_xw(const float* __restrict__ X,
                                                  const float* __restrict__ W) {
    extern __shared__ float sm1[];
    float* sX = sm1;
    float* sW = sm1 + 2 * 128 * 36;

    const int tid = threadIdx.x;
    const int lane = tid & 31, warp = tid >> 5;
    const int wr = warp & 3, wc = warp >> 2;
    const int m0 = blockIdx.y * 128, n0 = blockIdx.x * 128;
    const int r0 = lane >> 2, c0 = lane & 3;
    const int sel = lane >> 3, mrow = lane & 7;
    const int lrow = ((sel & 1) << 3) + mrow, lcol = (sel >> 1) << 2;
    const unsigned sX_u = (unsigned)__cvta_generic_to_shared(sX);

    float acc[2][8][4] = {};
    float4 xv[4], wv[4];

    auto ldg_stage = [&](int k0) {
#pragma unroll
        for (int p = 0; p < 4; p++) {
            int q = tid + p * 256;
            xv[p] = *(const float4*)&X[(size_t)(m0 + (q >> 3)) * IND + k0 + ((q & 7) << 2)];
            wv[p] = *(const float4*)&W[(size_t)(k0 + (q >> 5)) * OUTD + n0 + ((q & 31) << 2)];
        }
    };
    auto sts_stage = [&](int buf) {
#pragma unroll
        for (int p = 0; p < 4; p++) {
            int q = tid + p * 256;
            float4 t = make_float4(to_tf32(xv[p].x), to_tf32(xv[p].y),
                                   to_tf32(xv[p].z), to_tf32(xv[p].w));
            *(float4*)&sX[buf * 4608 + (q >> 3) * 36 + ((q & 7) << 2)] = t;
            float4 u = make_float4(to_tf32(wv[p].x), to_tf32(wv[p].y),
                                   to_tf32(wv[p].z), to_tf32(wv[p].w));
            *(float4*)&sW[buf * 4352 + (q >> 5) * 136 + ((q & 31) << 2)] = u;
        }
    };

    ldg_stage(0);
    sts_stage(0);
    __syncthreads();

    for (int s = 0; s < 16; s++) {
        const int buf = s & 1;
        if (s < 15) ldg_stage((s + 1) * 32);
#pragma unroll
        for (int k8 = 0; k8 < 4; k8++) {
            const int kb = k8 << 3;
            unsigned afr[2][4];
#pragma unroll
            for (int mt = 0; mt < 2; mt++) {
                unsigned addr = sX_u +
                    (buf * 4608 + (wr * 32 + mt * 16 + lrow) * 36 + kb + lcol) * 4u;
                ldsm4(afr[mt], addr);
            }
            const float* wp = &sW[buf * 4352 + (kb + c0) * 136 + wc * 64 + r0];
#pragma unroll
            for (int nt = 0; nt < 8; nt++) {
                unsigned b0 = __float_as_uint(wp[nt * 8]);
                unsigned b1 = __float_as_uint(wp[4 * 136 + nt * 8]);
#pragma unroll
                for (int mt = 0; mt < 2; mt++)
                    mma_tf32(acc[mt][nt], afr[mt], b0, b1);
            }
        }
        if (s < 15) {
            __syncthreads();
            sts_stage((s + 1) & 1);
            __syncthreads();
        }
    }
#pragma unroll
    for (int mt = 0; mt < 2; mt++)
#pragma unroll
        for (int nt = 0; nt < 8; nt++) {
            const int ra = wr * 32 + mt * 16 + r0;
            const int cb = wc * 64 + nt * 8 + c0 * 2;
            *(float2*)&g_h[(size_t)(m0 + ra) * OUTD + n0 + cb] =
                make_float2(acc[mt][nt][0], acc[mt][nt][1]);
            *(float2*)&g_h[(size_t)(m0 + ra + 8) * OUTD + n0 + cb] =
                make_float2(acc[mt][nt][2], acc[mt][nt][3]);
        }
}

// ---------------------------------------------------------------------------
// Kernel 2: as/an row dots (fp32); write g_h16 (fp16, k-paired layout).
// ---------------------------------------------------------------------------
__global__ __launch_bounds__(256) void k2_attvec(const float* __restrict__ a_self,
                                                 const float* __restrict__ a_neighs) {
    const int warp = threadIdx.x >> 5, lane = threadIdx.x & 31;
    const int row = blockIdx.x * 8 + warp;
    const float4* h4 = (const float4*)&g_h[(size_t)row * OUTD];
    __half* dst = &g_h16[(size_t)(row >> 1) * 512 + (row & 1)];
    float s1 = 0.f, s2 = 0.f;
#pragma unroll
    for (int q = 0; q < 2; q++) {
        float4 v = h4[lane + 32 * q];
        float4 a = ((const float4*)a_self)[lane + 32 * q];
        float4 b = ((const float4*)a_neighs)[lane + 32 * q];
        s1 += v.x * a.x + v.y * a.y + v.z * a.z + v.w * a.w;
        s2 += v.x * b.x + v.y * b.y + v.z * b.z + v.w * b.w;
        const int c = (lane + 32 * q) * 4;
        dst[(c + 0) * 2] = __float2half_rn(v.x);
        dst[(c + 1) * 2] = __float2half_rn(v.y);
        dst[(c + 2) * 2] = __float2half_rn(v.z);
        dst[(c + 3) * 2] = __float2half_rn(v.w);
    }
#pragma unroll
    for (int off = 16; off >= 1; off >>= 1) {
        s1 += __shfl_xor_sync(0xffffffffu, s1, off);
        s2 += __shfl_xor_sync(0xffffffffu, s2, off);
    }
    if (lane == 0) { g_as[row] = s1; g_an[row] = s2; }
}

// ---------------------------------------------------------------------------
// Kernel 3: fused masked-exp attention GEMM, fp16 m16n8k16 fp16-acc.
// 64 rows x 256 cols per CTA, 64 k-tiles of 128 j. grid 128, 256 thr.
// ---------------------------------------------------------------------------
#define SHU_STRIDE 260
#define SHU_BUF    (64 * SHU_STRIDE)
#define SP_STRIDE  136
#define SP_HBUF    (64 * SP_STRIDE)
#define SP_BYTE0   (2 * SHU_BUF * 4)
#define SAS_F      ((SP_BYTE0 + 2 * SP_HBUF * 2) / 4)
#define SRS_F      (SAS_F + 64)
#define K3_SMEM_BYTES ((SRS_F + 64) * 4)

__global__ __launch_bounds__(256) void k3_attn(const float* __restrict__ Adj,
                                               const float* __restrict__ Mg,
                                               float* __restrict__ Out) {
    extern __shared__ float sm[];
    uint32_t* sHu = (uint32_t*)sm;
    __half*   sPh = (__half*)((char*)sm + SP_BYTE0);
    float* s_as = sm + SAS_F;
    float* s_rs = sm + SRS_F;

    const int tid = threadIdx.x;
    const int lane = tid & 31, warp = tid >> 5;
    const int rowbase = blockIdx.x * 64;
    const int r0 = lane >> 2, c0 = lane & 3;
    const int g = tid >> 4, cbase = (tid & 15) << 3;
    const unsigned sP_u = (unsigned)__cvta_generic_to_shared(sPh);

    if (tid < 16)
        *(float4*)&s_as[tid * 4] = *(const float4*)&g_as[rowbase + tid * 4];

    auto stageH = [&](int tt) {
        const int b = tt & 1;
        const char* src = (const char*)g_h16 + (size_t)tt * 64 * 1024;
#pragma unroll
        for (int p = 0; p < 16; p++) {
            int ch = tid + p * 256;
            int pr = ch >> 6, c = ch & 63;
            cp16(&sHu[b * SHU_BUF + pr * SHU_STRIDE + c * 4],
                 src + (size_t)pr * 1024 + c * 16);
        }
        asm volatile("cp.async.commit_group;\n" ::: "memory");
    };

    float4 mreg[4][2], areg[4][2], ana, anb;
    auto ldgMA = [&](int tt) {
        const int jb = tt * JT;
        ana = *(const float4*)&g_an[jb + cbase];
        anb = *(const float4*)&g_an[jb + cbase + 4];
#pragma unroll
        for (int it = 0; it < 4; it++) {
            size_t goff = (size_t)(rowbase + g + (it << 4)) * NROWS + jb + cbase;
            mreg[it][0] = __ldg((const float4*)&Mg[goff]);
            mreg[it][1] = __ldg((const float4*)&Mg[goff + 4]);
            areg[it][0] = __ldg((const float4*)&Adj[goff]);
            areg[it][1] = __ldg((const float4*)&Adj[goff + 4]);
        }
    };

    float rsum[4] = {0.f, 0.f, 0.f, 0.f};

    // computeP for ONE row-group (it) of the next tile
    auto computePit = [&](int tt, int it) {
        const int b = tt & 1;
        const int r = g + (it << 4);
        const float asr = s_as[r];
        float p[8];
#pragma unroll
        for (int hh = 0; hh < 2; hh++) {
            float4 m4 = mreg[it][hh], a4 = areg[it][hh];
            float4 an = hh ? anb : ana;
            float t0 = (asr + an.x) * m4.x; t0 = t0 > 0.f ? t0 : 0.2f * t0;
            float t1 = (asr + an.y) * m4.y; t1 = t1 > 0.f ? t1 : 0.2f * t1;
            float t2 = (asr + an.z) * m4.z; t2 = t2 > 0.f ? t2 : 0.2f * t2;
            float t3 = (asr + an.w) * m4.w; t3 = t3 > 0.f ? t3 : 0.2f * t3;
            p[hh * 4 + 0] = a4.x > 0.f ? __expf(t0) : 0.f;
            p[hh * 4 + 1] = a4.y > 0.f ? __expf(t1) : 0.f;
            p[hh * 4 + 2] = a4.z > 0.f ? __expf(t2) : 0.f;
            p[hh * 4 + 3] = a4.w > 0.f ? __expf(t3) : 0.f;
        }
        rsum[it] += ((p[0] + p[1]) + (p[2] + p[3])) +
                    ((p[4] + p[5]) + (p[6] + p[7]));
        __half2 h01 = __floats2half2_rn(p[0] * PSCALE, p[1] * PSCALE);
        __half2 h23 = __floats2half2_rn(p[2] * PSCALE, p[3] * PSCALE);
        __half2 h45 = __floats2half2_rn(p[4] * PSCALE, p[5] * PSCALE);
        __half2 h67 = __floats2half2_rn(p[6] * PSCALE, p[7] * PSCALE);
        *(uint4*)&sPh[b * SP_HBUF + r * SP_STRIDE + cbase] =
            make_uint4(*(unsigned*)&h01, *(unsigned*)&h23,
                       *(unsigned*)&h45, *(unsigned*)&h67);
    };

    float acc[4][4][4] = {};   // fp32 masters

    // ---- prologue ----
    stageH(0);
    ldgMA(0);
    __syncthreads();
    computePit(0, 0); computePit(0, 1); computePit(0, 2); computePit(0, 3);
    asm volatile("cp.async.wait_group 0;\n" ::: "memory");
    __syncthreads();

    // ---- main loop: 64 iterations ----
    for (int t = 0; t < NTILE; t++) {
        const int b = t & 1;
        const bool more = (t < NTILE - 1);
        if (more) { stageH(t + 1); ldgMA(t + 1); }

        unsigned hacc[4][4][2] = {};   // fp16 tile accumulators (zeroed)
        {
            const int nb = warp * 32 + r0;
#pragma unroll
            for (int c16 = 0; c16 < 8; c16++) {
                unsigned afr[4][4];
#pragma unroll
                for (int mt = 0; mt < 4; mt++) {
                    unsigned addr = sP_u +
                        (b * SP_HBUF + (mt * 16 + (lane & 15)) * SP_STRIDE +
                         c16 * 16 + (lane >> 4) * 8) * 2u;
                    ldsm4(afr[mt], addr);
                }
                const uint32_t* hp =
                    &sHu[b * SHU_BUF + (c16 * 8 + c0) * SHU_STRIDE + nb];
#pragma unroll
                for (int nt = 0; nt < 4; nt++) {
                    unsigned b0 = hp[nt * 8];
                    unsigned b1 = hp[4 * SHU_STRIDE + nt * 8];
#pragma unroll
                    for (int mt = 0; mt < 4; mt++)
                        mma_f16a(hacc[mt][nt], afr[mt], b0, b1);
                }
                // interleave next-tile P computation under HMMA drain
                if ((c16 & 1) && more) computePit(t + 1, c16 >> 1);
            }
        }

        // promote fp16 tile accumulators into fp32 masters
#pragma unroll
        for (int mt = 0; mt < 4; mt++)
#pragma unroll
            for (int nt = 0; nt < 4; nt++) {
                float2 lo = __half22float2(*(__half2*)&hacc[mt][nt][0]);
                float2 hi = __half22float2(*(__half2*)&hacc[mt][nt][1]);
                acc[mt][nt][0] += lo.x; acc[mt][nt][1] += lo.y;
                acc[mt][nt][2] += hi.x; acc[mt][nt][3] += hi.y;
            }

        asm volatile("cp.async.wait_group 0;\n" ::: "memory");
        __syncthreads();
    }

    // ---- rowsum reduction (16 threads per row) ----
#pragma unroll
    for (int off = 8; off >= 1; off >>= 1)
#pragma unroll
        for (int it = 0; it < 4; it++)
            rsum[it] += __shfl_xor_sync(0xffffffffu, rsum[it], off);
    if ((lane & 15) == 0) {
#pragma unroll
        for (int it = 0; it < 4; it++) s_rs[g + (it << 4)] = rsum[it];
    }
    __syncthreads();

    // ---- epilogue: divide (undo 2^-6 scale), elu, store ----
#pragma unroll
    for (int mt = 0; mt < 4; mt++) {
        const int ra = mt * 16 + r0;
        const float ia = 64.0f / s_rs[ra];
        const float ib = 64.0f / s_rs[ra + 8];
#pragma unroll
        for (int nt = 0; nt < 4; nt++) {
            const int col = warp * 32 + nt * 8 + c0 * 2;
            float2 va = make_float2(elu_f(acc[mt][nt][0] * ia),
                                    elu_f(acc[mt][nt][1] * ia));
            float2 vb = make_float2(elu_f(acc[mt][nt][2] * ib),
                                    elu_f(acc[mt][nt][3] * ib));
            *(float2*)&Out[(size_t)(rowbase + ra) * OUTD + col] = va;
            *(float2*)&Out[(size_t)(rowbase + ra + 8) * OUTD + col] = vb;
        }
    }
}

// ---------------------------------------------------------------------------
extern "C" void kernel_launch(void* const* d_in, const int* in_sizes, int n_in,
                              void* d_out, int out_size) {
    const float* X        = (const float*)d_in[0];
    const float* Adj      = (const float*)d_in[1];
    const float* Mg       = (const float*)d_in[2];
    const float* W        = (const float*)d_in[3];
    const float* a_self   = (const float*)d_in[4];
    const float* a_neighs = (const float*)d_in[5];
    float* Out = (float*)d_out;

    cudaFuncSetAttribute(k1_gemm_xw, cudaFuncAttributeMaxDynamicSharedMemorySize,
                         K1_SMEM_BYTES);
    cudaFuncSetAttribute(k3_attn, cudaFuncAttributeMaxDynamicSharedMemorySize,
                         K3_SMEM_BYTES);

    k1_gemm_xw<<<dim3(2, 64), 256, K1_SMEM_BYTES>>>(X, W);
    k2_attvec<<<1024, 256>>>(a_self, a_neighs);
    k3_attn<<<128, 256, K3_SMEM_BYTES>>>(Adj, Mg, Out);
}

// round 11
// speedup vs baseline: 1.6186x; 1.0277x over previous
#include <cuda_runtime.h>
#include <cuda_fp16.h>
#include <cstdint>

// ---------------------------------------------------------------------------
// GAT layer (sm_100 base target — legacy mma.sync only):
//   k1: H = X @ W                      (tf32 mma.sync m16n8k8, 27us)
//   k2: as/an row dots (fp32); emit g_h16 = fp16 H in k-paired layout
//   k3: Out = elu( (P @ H) / rowsum(P) )  via fp16 mma.sync m16n8k16
//       fp16 tile accumulate -> fp32 masters. 32 rows x 256 cols per CTA,
//       JT=64, grid 256 => ~2 CTAs/SM (4 warps/SMSP) for latency hiding.
// ---------------------------------------------------------------------------

#define NROWS 8192
#define IND   512
#define OUTD  256
#define JT    64
#define NTILE (NROWS / JT)     // 128

__device__ __align__(16) float  g_h  [NROWS * OUTD];
__device__ __align__(16) __half g_h16[NROWS * OUTD];   // word[jpair*256+n] = {h[2j][n], h[2j+1][n]}
__device__ __align__(16) float  g_as [NROWS];
__device__ __align__(16) float  g_an [NROWS];

#define PSCALE 0.015625f   // 2^-6

// ---------------------------------------------------------------------------
__device__ __forceinline__ float to_tf32(float x) {
    unsigned r;
    asm("cvt.rna.tf32.f32 %0, %1;\n" : "=r"(r) : "f"(x));
    return __uint_as_float(r);
}
__device__ __forceinline__ void mma_tf32(float* d, const unsigned* a,
                                         unsigned b0, unsigned b1) {
    asm volatile(
        "mma.sync.aligned.m16n8k8.row.col.f32.tf32.tf32.f32 "
        "{%0,%1,%2,%3}, {%4,%5,%6,%7}, {%8,%9}, {%0,%1,%2,%3};\n"
        : "+f"(d[0]), "+f"(d[1]), "+f"(d[2]), "+f"(d[3])
        : "r"(a[0]), "r"(a[1]), "r"(a[2]), "r"(a[3]), "r"(b0), "r"(b1));
}
__device__ __forceinline__ void mma_f16a(unsigned* d, const unsigned* a,
                                         unsigned b0, unsigned b1) {
    asm volatile(
        "mma.sync.aligned.m16n8k16.row.col.f16.f16.f16.f16 "
        "{%0,%1}, {%2,%3,%4,%5}, {%6,%7}, {%0,%1};\n"
        : "+r"(d[0]), "+r"(d[1])
        : "r"(a[0]), "r"(a[1]), "r"(a[2]), "r"(a[3]), "r"(b0), "r"(b1));
}
__device__ __forceinline__ void ldsm4(unsigned* a, unsigned addr) {
    asm volatile(
        "ldmatrix.sync.aligned.m8n8.x4.shared.b16 {%0,%1,%2,%3}, [%4];\n"
        : "=r"(a[0]), "=r"(a[1]), "=r"(a[2]), "=r"(a[3]) : "r"(addr));
}
__device__ __forceinline__ void cp16(void* smem, const void* g) {
    unsigned s = (unsigned)__cvta_generic_to_shared(smem);
    asm volatile("cp.async.cg.shared.global [%0], [%1], 16;\n" :: "r"(s), "l"(g));
}
__device__ __forceinline__ float elu_f(float x) { return x > 0.f ? x : expm1f(x); }

// ---------------------------------------------------------------------------
// Kernel 1: H = X @ W, tf32 mma.sync (R6-proven, 27us). grid (2, 64).
// ---------------------------------------------------------------------------
#define K1_SMEM_BYTES ((2 * 128 * 36 + 2 * 32 * 136) * 4)

__global__ __launch_bounds__(256) void k1_gemm_xw(const float* __restrict__ X,
                                                  const float* __restrict__ W) {
    extern __shared__ float sm1[];
    float* sX = sm1;
    float* sW = sm1 + 2 * 128 * 36;

    const int tid = threadIdx.x;
    const int lane = tid & 31, warp = tid >> 5;
    const int wr = warp & 3, wc = warp >> 2;
    const int m0 = blockIdx.y * 128, n0 = blockIdx.x * 128;
    const int r0 = lane >> 2, c0 = lane & 3;
    const int sel = lane >> 3, mrow = lane & 7;
    const int lrow = ((sel & 1) << 3) + mrow, lcol = (sel >> 1) << 2;
    const unsigned sX_u = (unsigned)__cvta_generic_to_shared(sX);

    float acc[2][8][4] = {};
    float4 xv[4], wv[4];

    auto ldg_stage = [&](int k0) {
#pragma unroll
        for (int p = 0; p < 4; p++) {
            int q = tid + p * 256;
            xv[p] = *(const float4*)&X[(size_t)(m0 + (q >> 3)) * IND + k0 + ((q & 7) << 2)];
            wv[p] = *(const float4*)&W[(size_t)(k0 + (q >> 5)) * OUTD + n0 + ((q & 31) << 2)];
        }
    };
    auto sts_stage = [&](int buf) {
#pragma unroll
        for (int p = 0; p < 4; p++) {
            int q = tid + p * 256;
            float4 t = make_float4(to_tf32(xv[p].x), to_tf32(xv[p].y),
                                   to_tf32(xv[p].z), to_tf32(xv[p].w));
            *(float4*)&sX[buf * 4608 + (q >> 3) * 36 + ((q & 7) << 2)] = t;
            float4 u = make_float4(to_tf32(wv[p].x), to_tf32(wv[p].y),
                                   to_tf32(wv[p].z), to_tf32(wv[p].w));
            *(float4*)&sW[buf * 4352 + (q >> 5) * 136 + ((q & 31) << 2)] = u;
        }
    };

    ldg_stage(0);
    sts_stage(0);
    __syncthreads();

    for (int s = 0; s < 16; s++) {
        const int buf = s & 1;
        if (s < 15) ldg_stage((s + 1) * 32);
#pragma unroll
        for (int k8 = 0; k8 < 4; k8++) {
            const int kb = k8 << 3;
            unsigned afr[2][4];
#pragma unroll
            for (int mt = 0; mt < 2; mt++) {
                unsigned addr = sX_u +
                    (buf * 4608 + (wr * 32 + mt * 16 + lrow) * 36 + kb + lcol) * 4u;
                ldsm4(afr[mt], addr);
            }
            const float* wp = &sW[buf * 4352 + (kb + c0) * 136 + wc * 64 + r0];
#pragma unroll
            for (int nt = 0; nt < 8; nt++) {
                unsigned b0 = __float_as_uint(wp[nt * 8]);
                unsigned b1 = __float_as_uint(wp[4 * 136 + nt * 8]);
#pragma unroll
                for (int mt = 0; mt < 2; mt++)
                    mma_tf32(acc[mt][nt], afr[mt], b0, b1);
            }
        }
        if (s < 15) {
            __syncthreads();
            sts_stage((s + 1) & 1);
            __syncthreads();
        }
    }
#pragma unroll
    for (int mt = 0; mt < 2; mt++)
#pragma unroll
        for (int nt = 0; nt < 8; nt++) {
            const int ra = wr * 32 + mt * 16 + r0;
            const int cb = wc * 64 + nt * 8 + c0 * 2;
            *(float2*)&g_h[(size_t)(m0 + ra) * OUTD + n0 + cb] =
                make_float2(acc[mt][nt][0], acc[mt][nt][1]);
            *(float2*)&g_h[(size_t)(m0 + ra + 8) * OUTD + n0 + cb] =
                make_float2(acc[mt][nt][2], acc[mt][nt][3]);
        }
}

// ---------------------------------------------------------------------------
// Kernel 2: as/an row dots (fp32); write g_h16 (fp16, k-paired layout).
// ---------------------------------------------------------------------------
__global__ __launch_bounds__(256) void k2_attvec(const float* __restrict__ a_self,
                                                 const float* __restrict__ a_neighs) {
    const int warp = threadIdx.x >> 5, lane = threadIdx.x & 31;
    const int row = blockIdx.x * 8 + warp;
    const float4* h4 = (const float4*)&g_h[(size_t)row * OUTD];
    __half* dst = &g_h16[(size_t)(row >> 1) * 512 + (row & 1)];
    float s1 = 0.f, s2 = 0.f;
#pragma unroll
    for (int q = 0; q < 2; q++) {
        float4 v = h4[lane + 32 * q];
        float4 a = ((const float4*)a_self)[lane + 32 * q];
        float4 b = ((const float4*)a_neighs)[lane + 32 * q];
        s1 += v.x * a.x + v.y * a.y + v.z * a.z + v.w * a.w;
        s2 += v.x * b.x + v.y * b.y + v.z * b.z + v.w * b.w;
        const int c = (lane + 32 * q) * 4;
        dst[(c + 0) * 2] = __float2half_rn(v.x);
        dst[(c + 1) * 2] = __float2half_rn(v.y);
        dst[(c + 2) * 2] = __float2half_rn(v.z);
        dst[(c + 3) * 2] = __float2half_rn(v.w);
    }
#pragma unroll
    for (int off = 16; off >= 1; off >>= 1) {
        s1 += __shfl_xor_sync(0xffffffffu, s1, off);
        s2 += __shfl_xor_sync(0xffffffffu, s2, off);
    }
    if (lane == 0) { g_as[row] = s1; g_an[row] = s2; }
}

// ---------------------------------------------------------------------------
// Kernel 3: fused masked-exp attention GEMM, fp16 m16n8k16 fp16-acc.
// 32 rows x 256 cols per CTA, 128 k-tiles of 64 j. grid 256, 256 thr.
// smem ~76KB -> 2 CTAs/SM.
// ---------------------------------------------------------------------------
#define SHU_STRIDE 260
#define SHU_BUF    (32 * SHU_STRIDE)          // u32 per buffer
#define SP_STRIDE  72                         // halves per row
#define SP_HBUF    (32 * SP_STRIDE)           // halves per buffer
#define SP_BYTE0   (2 * SHU_BUF * 4)          // 66560
#define SAS_F      ((SP_BYTE0 + 2 * SP_HBUF * 2) / 4)   // float idx 18944
#define SRS_F      (SAS_F + 32)
#define K3_SMEM_BYTES ((SRS_F + 32) * 4)      // 76032

__global__ __launch_bounds__(256, 2) void k3_attn(const float* __restrict__ Adj,
                                                  const float* __restrict__ Mg,
                                                  float* __restrict__ Out) {
    extern __shared__ float sm[];
    uint32_t* sHu = (uint32_t*)sm;
    __half*   sPh = (__half*)((char*)sm + SP_BYTE0);
    float* s_as = sm + SAS_F;
    float* s_rs = sm + SRS_F;

    const int tid = threadIdx.x;
    const int lane = tid & 31, warp = tid >> 5;
    const int rowbase = blockIdx.x * 32;
    const int r0 = lane >> 2, c0 = lane & 3;
    const int g = tid >> 3, cbase = (tid & 7) << 3;   // row g, 8 cols per thread
    const unsigned sP_u = (unsigned)__cvta_generic_to_shared(sPh);

    if (tid < 8)
        *(float4*)&s_as[tid * 4] = *(const float4*)&g_as[rowbase + tid * 4];

    auto stageH = [&](int tt) {
        const int b = tt & 1;
        const char* src = (const char*)g_h16 + (size_t)tt * 32 * 1024;
#pragma unroll
        for (int p = 0; p < 8; p++) {
            int ch = tid + p * 256;
            int pr = ch >> 6, c = ch & 63;
            cp16(&sHu[b * SHU_BUF + pr * SHU_STRIDE + c * 4],
                 src + (size_t)pr * 1024 + c * 16);
        }
        asm volatile("cp.async.commit_group;\n" ::: "memory");
    };

    float4 mreg[2], areg[2], ana, anb;
    auto ldgMA = [&](int tt) {
        const int jb = tt * JT;
        ana = *(const float4*)&g_an[jb + cbase];
        anb = *(const float4*)&g_an[jb + cbase + 4];
        size_t goff = (size_t)(rowbase + g) * NROWS + jb + cbase;
        mreg[0] = __ldg((const float4*)&Mg[goff]);
        mreg[1] = __ldg((const float4*)&Mg[goff + 4]);
        areg[0] = __ldg((const float4*)&Adj[goff]);
        areg[1] = __ldg((const float4*)&Adj[goff + 4]);
    };

    float rsum = 0.f;

    auto computeP = [&](int tt) {
        const int b = tt & 1;
        const float asr = s_as[g];
        float p[8];
#pragma unroll
        for (int hh = 0; hh < 2; hh++) {
            float4 m4 = mreg[hh], a4 = areg[hh];
            float4 an = hh ? anb : ana;
            float t0 = (asr + an.x) * m4.x; t0 = t0 > 0.f ? t0 : 0.2f * t0;
            float t1 = (asr + an.y) * m4.y; t1 = t1 > 0.f ? t1 : 0.2f * t1;
            float t2 = (asr + an.z) * m4.z; t2 = t2 > 0.f ? t2 : 0.2f * t2;
            float t3 = (asr + an.w) * m4.w; t3 = t3 > 0.f ? t3 : 0.2f * t3;
            p[hh * 4 + 0] = a4.x > 0.f ? __expf(t0) : 0.f;
            p[hh * 4 + 1] = a4.y > 0.f ? __expf(t1) : 0.f;
            p[hh * 4 + 2] = a4.z > 0.f ? __expf(t2) : 0.f;
            p[hh * 4 + 3] = a4.w > 0.f ? __expf(t3) : 0.f;
        }
        rsum += ((p[0] + p[1]) + (p[2] + p[3])) +
                ((p[4] + p[5]) + (p[6] + p[7]));
        __half2 h01 = __floats2half2_rn(p[0] * PSCALE, p[1] * PSCALE);
        __half2 h23 = __floats2half2_rn(p[2] * PSCALE, p[3] * PSCALE);
        __half2 h45 = __floats2half2_rn(p[4] * PSCALE, p[5] * PSCALE);
        __half2 h67 = __floats2half2_rn(p[6] * PSCALE, p[7] * PSCALE);
        *(uint4*)&sPh[b * SP_HBUF + g * SP_STRIDE + cbase] =
            make_uint4(*(unsigned*)&h01, *(unsigned*)&h23,
                       *(unsigned*)&h45, *(unsigned*)&h67);
    };

    float acc[2][4][4] = {};   // fp32 masters: 2 m-tiles x 4 n-tiles

    // ---- prologue ----
    stageH(0);
    ldgMA(0);
    __syncthreads();
    computeP(0);
    asm volatile("cp.async.wait_group 0;\n" ::: "memory");
    __syncthreads();

    // ---- main loop: 128 iterations ----
    for (int t = 0; t < NTILE; t++) {
        const int b = t & 1;
        const bool more = (t < NTILE - 1);
        if (more) { stageH(t + 1); ldgMA(t + 1); }

        unsigned hacc[2][4][2] = {};   // fp16 tile accumulators
        {
            const int nb = warp * 32 + r0;
#pragma unroll
            for (int c16 = 0; c16 < 4; c16++) {
                unsigned afr[2][4];
#pragma unroll
                for (int mt = 0; mt < 2; mt++) {
                    unsigned addr = sP_u +
                        (b * SP_HBUF + (mt * 16 + (lane & 15)) * SP_STRIDE +
                         c16 * 16 + (lane >> 4) * 8) * 2u;
                    ldsm4(afr[mt], addr);
                }
                const uint32_t* hp =
                    &sHu[b * SHU_BUF + (c16 * 8 + c0) * SHU_STRIDE + nb];
#pragma unroll
                for (int nt = 0; nt < 4; nt++) {
                    unsigned b0 = hp[nt * 8];
                    unsigned b1 = hp[4 * SHU_STRIDE + nt * 8];
#pragma unroll
                    for (int mt = 0; mt < 2; mt++)
                        mma_f16a(hacc[mt][nt], afr[mt], b0, b1);
                }
                if (c16 == 1 && more) computeP(t + 1);  // overlap exp with HMMA
            }
        }

        // promote fp16 tile accumulators into fp32 masters
#pragma unroll
        for (int mt = 0; mt < 2; mt++)
#pragma unroll
            for (int nt = 0; nt < 4; nt++) {
                float2 lo = __half22float2(*(__half2*)&hacc[mt][nt][0]);
                float2 hi = __half22float2(*(__half2*)&hacc[mt][nt][1]);
                acc[mt][nt][0] += lo.x; acc[mt][nt][1] += lo.y;
                acc[mt][nt][2] += hi.x; acc[mt][nt][3] += hi.y;
            }

        asm volatile("cp.async.wait_group 0;\n" ::: "memory");
        __syncthreads();
    }

    // ---- rowsum reduction (8 threads per row, same warp) ----
#pragma unroll
    for (int off = 4; off >= 1; off >>= 1)
        rsum += __shfl_xor_sync(0xffffffffu, rsum, off);
    if ((tid & 7) == 0) s_rs[g] = rsum;
    __syncthreads();

    // ---- epilogue: divide (undo 2^-6 scale), elu, store ----
#pragma unroll
    for (int mt = 0; mt < 2; mt++) {
        const int ra = mt * 16 + r0;
        const float ia = 64.0f / s_rs[ra];
        const float ib = 64.0f / s_rs[ra + 8];
#pragma unroll
        for (int nt = 0; nt < 4; nt++) {
            const int col = warp * 32 + nt * 8 + c0 * 2;
            float2 va = make_float2(elu_f(acc[mt][nt][0] * ia),
                                    elu_f(acc[mt][nt][1] * ia));
            float2 vb = make_float2(elu_f(acc[mt][nt][2] * ib),
                                    elu_f(acc[mt][nt][3] * ib));
            *(float2*)&Out[(size_t)(rowbase + ra) * OUTD + col] = va;
            *(float2*)&Out[(size_t)(rowbase + ra + 8) * OUTD + col] = vb;
        }
    }
}

// ---------------------------------------------------------------------------
extern "C" void kernel_launch(void* const* d_in, const int* in_sizes, int n_in,
                              void* d_out, int out_size) {
    const float* X        = (const float*)d_in[0];
    const float* Adj      = (const float*)d_in[1];
    const float* Mg       = (const float*)d_in[2];
    const float* W        = (const float*)d_in[3];
    const float* a_self   = (const float*)d_in[4];
    const float* a_neighs = (const float*)d_in[5];
    float* Out = (float*)d_out;

    cudaFuncSetAttribute(k1_gemm_xw, cudaFuncAttributeMaxDynamicSharedMemorySize,
                         K1_SMEM_BYTES);
    cudaFuncSetAttribute(k3_attn, cudaFuncAttributeMaxDynamicSharedMemorySize,
                         K3_SMEM_BYTES);

    k1_gemm_xw<<<dim3(2, 64), 256, K1_SMEM_BYTES>>>(X, W);
    k2_attvec<<<1024, 256>>>(a_self, a_neighs);
    k3_attn<<<256, 256, K3_SMEM_BYTES>>>(Adj, Mg, Out);
}